// round 1
// baseline (speedup 1.0000x reference)
#include <cuda_runtime.h>
#include <cstdint>

#define Gb   32      // B*H
#define Hh   8
#define Nn   4096
#define Dd   64
#define Mm   256
#define Ll   16
#define PITERS 6
#define KC   33

// ---------------- scratch (static __device__, allowed by harness) ----------------
__device__ float g_ql  [Gb*Mm*Dd];
__device__ float g_kl  [Gb*Mm*Dd];
__device__ float g_x   [Gb*Mm*Mm];          // attn2 (softmaxed)
__device__ float g_za  [Gb*Mm*Mm];
__device__ float g_zb  [Gb*Mm*Mm];
__device__ float g_A   [Gb*Mm*Mm];          // xz
__device__ float g_T1  [Gb*Mm*Mm];
__device__ float g_T2  [Gb*Mm*Mm];
__device__ float g_t3v [Gb*Mm*Dd];
__device__ float g_y   [Gb*Mm*Dd];
__device__ float g_attn3[(size_t)Gb*Mm*Nn]; // 128 MB
__device__ float g_attn1[(size_t)Gb*Nn*Mm]; // 128 MB
__device__ float g_colsum[Gb*Mm];
__device__ unsigned int g_maxbits[2];       // [0]=max row-sum, [1]=max col-sum (float bits)

// ---------------- helpers ----------------
__device__ __forceinline__ float blkmax(float v, float* sred) {
    int t = threadIdx.x; sred[t] = v; __syncthreads();
    for (int s = 128; s > 0; s >>= 1) { if (t < s) sred[t] = fmaxf(sred[t], sred[t+s]); __syncthreads(); }
    float r = sred[0]; __syncthreads(); return r;
}
__device__ __forceinline__ float blksum(float v, float* sred) {
    int t = threadIdx.x; sred[t] = v; __syncthreads();
    for (int s = 128; s > 0; s >>= 1) { if (t < s) sred[t] += sred[t+s]; __syncthreads(); }
    float r = sred[0]; __syncthreads(); return r;
}

// ---------------- init: zero stats + t3v ----------------
__global__ void k_init() {
    int idx = blockIdx.x*256 + threadIdx.x;
    if (idx < Gb*Mm*Dd) g_t3v[idx] = 0.f;
    if (idx < Gb*Mm)    g_colsum[idx] = 0.f;
    if (idx < 2)        g_maxbits[idx] = 0u;
}

// ---------------- landmarks: ql = mean(q)*scale, kl = mean(k) ----------------
__global__ void __launch_bounds__(256) k_landmark(const float* __restrict__ q,
                                                  const float* __restrict__ k) {
    int idx = blockIdx.x*256 + threadIdx.x;
    if (idx >= Gb*Mm*Dd) return;
    int d = idx & 63; int m = (idx >> 6) & 255; int g = idx >> 14;
    size_t base = ((size_t)g*Nn + (size_t)m*Ll)*Dd + d;
    float sq = 0.f, sk = 0.f;
    #pragma unroll
    for (int l = 0; l < Ll; l++) { sq += q[base + (size_t)l*Dd]; sk += k[base + (size_t)l*Dd]; }
    g_ql[idx] = sq * (0.125f / 16.f);   // * D^-0.5 / L
    g_kl[idx] = sk * (1.f / 16.f);
}

// ---------------- attn2 = softmax(ql @ kl^T), + row/col-sum stats ----------------
__global__ void __launch_bounds__(256) k_attn2() {
    __shared__ float qrow[Dd];
    __shared__ float sred[256];
    int i = blockIdx.x, g = blockIdx.y, j = threadIdx.x;
    if (threadIdx.x < Dd) qrow[threadIdx.x] = g_ql[((size_t)g*Mm + i)*Dd + threadIdx.x];
    __syncthreads();
    const float4* kr = (const float4*)(g_kl + ((size_t)g*Mm + j)*Dd);
    float s = 0.f;
    #pragma unroll
    for (int d4 = 0; d4 < 16; d4++) {
        float4 kv = kr[d4];
        s += qrow[d4*4+0]*kv.x + qrow[d4*4+1]*kv.y + qrow[d4*4+2]*kv.z + qrow[d4*4+3]*kv.w;
    }
    float mx = blkmax(s, sred);
    float e  = __expf(s - mx);
    float S  = blksum(e, sred);
    float val = e / S;
    g_x[((size_t)g*Mm + i)*Mm + j] = val;
    atomicAdd(&g_colsum[g*Mm + j], val);
    float rowsum = blksum(val, sred);
    if (threadIdx.x == 0) atomicMax(&g_maxbits[0], __float_as_uint(rowsum));
}

__global__ void k_colmax() {
    __shared__ float sred[256];
    float mx = 0.f;
    for (int i = threadIdx.x; i < Gb*Mm; i += 256) mx = fmaxf(mx, g_colsum[i]);
    mx = blkmax(mx, sred);
    if (threadIdx.x == 0) atomicMax(&g_maxbits[1], __float_as_uint(mx));
}

// ---------------- z0 = attn2^T / (max_rowsum * max_colsum) ----------------
__global__ void __launch_bounds__(256) k_zinit() {
    int idx = blockIdx.x*256 + threadIdx.x;
    if (idx >= Gb*Mm*Mm) return;
    float denom = __uint_as_float(g_maxbits[0]) * __uint_as_float(g_maxbits[1]);
    int j = idx & 255; int i = (idx >> 8) & 255; int g = idx >> 16;
    g_za[idx] = g_x[((size_t)g*Mm + j)*Mm + i] / denom;
}

// ---------------- batched 256x256x256 SGEMM: C = s*(A@B) + p*A + q*I ----------------
__global__ void __launch_bounds__(256) k_gemm256(const float* __restrict__ Ab,
                                                 const float* __restrict__ Bb,
                                                 float* __restrict__ Cb,
                                                 float s, float pc, float qc) {
    int g = blockIdx.z;
    const float* A = Ab + (size_t)g*Mm*Mm;
    const float* B = Bb + (size_t)g*Mm*Mm;
    float*       C = Cb + (size_t)g*Mm*Mm;
    __shared__ float As[16][68];
    __shared__ float Bs[16][64];
    int tid = threadIdx.x;
    int tx = tid & 15, ty = tid >> 4;
    int row0 = blockIdx.y*64, col0 = blockIdx.x*64;
    int ai = tid >> 2, ak = (tid*4) & 15;
    int bk = tid >> 4, bj = (tid*4) & 63;
    float c[4][4] = {};
    for (int k0 = 0; k0 < 256; k0 += 16) {
        float4 av = *(const float4*)(A + (size_t)(row0+ai)*256 + k0 + ak);
        As[ak+0][ai]=av.x; As[ak+1][ai]=av.y; As[ak+2][ai]=av.z; As[ak+3][ai]=av.w;
        *(float4*)&Bs[bk][bj] = *(const float4*)(B + (size_t)(k0+bk)*256 + col0 + bj);
        __syncthreads();
        #pragma unroll
        for (int kk = 0; kk < 16; kk++) {
            float4 a = *(const float4*)&As[kk][ty*4];
            float4 b = *(const float4*)&Bs[kk][tx*4];
            c[0][0]+=a.x*b.x; c[0][1]+=a.x*b.y; c[0][2]+=a.x*b.z; c[0][3]+=a.x*b.w;
            c[1][0]+=a.y*b.x; c[1][1]+=a.y*b.y; c[1][2]+=a.y*b.z; c[1][3]+=a.y*b.w;
            c[2][0]+=a.z*b.x; c[2][1]+=a.z*b.y; c[2][2]+=a.z*b.z; c[2][3]+=a.z*b.w;
            c[3][0]+=a.w*b.x; c[3][1]+=a.w*b.y; c[3][2]+=a.w*b.z; c[3][3]+=a.w*b.w;
        }
        __syncthreads();
    }
    #pragma unroll
    for (int ii = 0; ii < 4; ii++) {
        int i = row0 + ty*4 + ii;
        #pragma unroll
        for (int jj = 0; jj < 4; jj++) {
            int j = col0 + tx*4 + jj;
            float v = s * c[ii][jj];
            if (pc != 0.f) v += pc * A[(size_t)i*256 + j];
            if (qc != 0.f && i == j) v += qc;
            C[(size_t)i*256 + j] = v;
        }
    }
}

// ---------------- NT GEMM (K=64): C[rows,cols] = alpha * A[rows,64] @ B[cols,64]^T ----------------
__global__ void __launch_bounds__(256) k_gemm_nt(const float* __restrict__ Ab, size_t Astr,
                                                 const float* __restrict__ Bb, size_t Bstr,
                                                 float* __restrict__ Cb, size_t Cstr,
                                                 int ldc, float alpha) {
    int g = blockIdx.z;
    const float* A = Ab + (size_t)g*Astr;
    const float* B = Bb + (size_t)g*Bstr;
    float*       C = Cb + (size_t)g*Cstr;
    __shared__ float As[16][68];
    __shared__ float Bs[16][68];
    int tid = threadIdx.x;
    int tx = tid & 15, ty = tid >> 4;
    int row0 = blockIdx.y*64, col0 = blockIdx.x*64;
    int ai = tid >> 2, ak = (tid*4) & 15;
    float c[4][4] = {};
    for (int k0 = 0; k0 < 64; k0 += 16) {
        float4 av = *(const float4*)(A + (size_t)(row0+ai)*64 + k0 + ak);
        As[ak+0][ai]=av.x; As[ak+1][ai]=av.y; As[ak+2][ai]=av.z; As[ak+3][ai]=av.w;
        float4 bv = *(const float4*)(B + (size_t)(col0+ai)*64 + k0 + ak);
        Bs[ak+0][ai]=bv.x; Bs[ak+1][ai]=bv.y; Bs[ak+2][ai]=bv.z; Bs[ak+3][ai]=bv.w;
        __syncthreads();
        #pragma unroll
        for (int kk = 0; kk < 16; kk++) {
            float4 a = *(const float4*)&As[kk][ty*4];
            float4 b = *(const float4*)&Bs[kk][tx*4];
            c[0][0]+=a.x*b.x; c[0][1]+=a.x*b.y; c[0][2]+=a.x*b.z; c[0][3]+=a.x*b.w;
            c[1][0]+=a.y*b.x; c[1][1]+=a.y*b.y; c[1][2]+=a.y*b.z; c[1][3]+=a.y*b.w;
            c[2][0]+=a.z*b.x; c[2][1]+=a.z*b.y; c[2][2]+=a.z*b.z; c[2][3]+=a.z*b.w;
            c[3][0]+=a.w*b.x; c[3][1]+=a.w*b.y; c[3][2]+=a.w*b.z; c[3][3]+=a.w*b.w;
        }
        __syncthreads();
    }
    #pragma unroll
    for (int ii = 0; ii < 4; ii++) {
        int i = row0 + ty*4 + ii;
        #pragma unroll
        for (int jj = 0; jj < 4; jj++)
            C[(size_t)i*ldc + col0 + tx*4 + jj] = alpha * c[ii][jj];
    }
}

// ---------------- row softmax (cols <= 4096) ----------------
__global__ void __launch_bounds__(256) k_softmax(float* __restrict__ mat, int cols) {
    __shared__ float buf[4096];
    __shared__ float sred[256];
    size_t r = blockIdx.x;
    float* p = mat + r * (size_t)cols;
    int t = threadIdx.x;
    float mx = -1e30f;
    for (int i = t; i < cols; i += 256) { float v = p[i]; buf[i] = v; mx = fmaxf(mx, v); }
    mx = blkmax(mx, sred);
    float s = 0.f;
    for (int i = t; i < cols; i += 256) { float e = __expf(buf[i] - mx); buf[i] = e; s += e; }
    s = blksum(s, sred);
    float inv = 1.f / s;
    for (int i = t; i < cols; i += 256) p[i] = buf[i] * inv;
}

// ---------------- AV GEMM: C[rows,64] (+)= A[rows,K] @ B[K,64], optional split-K atomics ----------------
__global__ void __launch_bounds__(256) k_av(const float* __restrict__ Ab, size_t Astr, int lda,
                                            const float* __restrict__ Bb, size_t Bstr,
                                            float* __restrict__ Cb, size_t Cstr,
                                            int K, int nsplit, int doAtomic) {
    int g = blockIdx.z;
    const float* A = Ab + (size_t)g*Astr;
    const float* B = Bb + (size_t)g*Bstr;
    float*       C = Cb + (size_t)g*Cstr;
    __shared__ float As[16][68];
    __shared__ float Bs[16][64];
    int tid = threadIdx.x;
    int tx = tid & 15, ty = tid >> 4;
    int row0 = blockIdx.y*64;
    int kchunk = K / nsplit;
    int kbeg = blockIdx.x * kchunk, kend = kbeg + kchunk;
    int ai = tid >> 2, ak = (tid*4) & 15;
    int bk = tid >> 4, bj = (tid*4) & 63;
    float c[4][4] = {};
    for (int k0 = kbeg; k0 < kend; k0 += 16) {
        float4 av = *(const float4*)(A + (size_t)(row0+ai)*lda + k0 + ak);
        As[ak+0][ai]=av.x; As[ak+1][ai]=av.y; As[ak+2][ai]=av.z; As[ak+3][ai]=av.w;
        *(float4*)&Bs[bk][bj] = *(const float4*)(B + (size_t)(k0+bk)*64 + bj);
        __syncthreads();
        #pragma unroll
        for (int kk = 0; kk < 16; kk++) {
            float4 a = *(const float4*)&As[kk][ty*4];
            float4 b = *(const float4*)&Bs[kk][tx*4];
            c[0][0]+=a.x*b.x; c[0][1]+=a.x*b.y; c[0][2]+=a.x*b.z; c[0][3]+=a.x*b.w;
            c[1][0]+=a.y*b.x; c[1][1]+=a.y*b.y; c[1][2]+=a.y*b.z; c[1][3]+=a.y*b.w;
            c[2][0]+=a.z*b.x; c[2][1]+=a.z*b.y; c[2][2]+=a.z*b.z; c[2][3]+=a.z*b.w;
            c[3][0]+=a.w*b.x; c[3][1]+=a.w*b.y; c[3][2]+=a.w*b.z; c[3][3]+=a.w*b.w;
        }
        __syncthreads();
    }
    #pragma unroll
    for (int ii = 0; ii < 4; ii++) {
        int i = row0 + ty*4 + ii;
        #pragma unroll
        for (int jj = 0; jj < 4; jj++) {
            float* dst = &C[(size_t)i*64 + tx*4 + jj];
            if (doAtomic) atomicAdd(dst, c[ii][jj]); else *dst = c[ii][jj];
        }
    }
}

// ---------------- depthwise residual conv: out += conv_n(v, w[h]) ----------------
__global__ void __launch_bounds__(256) k_conv(const float* __restrict__ v,
                                              const float* __restrict__ w,
                                              float* __restrict__ out) {
    __shared__ float sv[96][64];
    __shared__ float sw[KC];
    int g = blockIdx.y, h = g & (Hh-1);
    int n0 = blockIdx.x * 64;
    const float* vb = v + (size_t)g*Nn*Dd;
    for (int idx = threadIdx.x; idx < 96*64; idx += 256) {
        int r = idx >> 6, d = idx & 63;
        int n = n0 - 16 + r;
        sv[r][d] = (n >= 0 && n < Nn) ? vb[(size_t)n*64 + d] : 0.f;
    }
    if (threadIdx.x < KC) sw[threadIdx.x] = w[h*KC + threadIdx.x];
    __syncthreads();
    for (int idx = threadIdx.x; idx < 64*64; idx += 256) {
        int r = idx >> 6, d = idx & 63;
        float acc = 0.f;
        #pragma unroll
        for (int t = 0; t < KC; t++) acc += sw[t] * sv[r+t][d];
        out[(size_t)g*Nn*Dd + (size_t)(n0+r)*64 + d] += acc;
    }
}

// ---------------- launch ----------------
extern "C" void kernel_launch(void* const* d_in, const int* in_sizes, int n_in,
                              void* d_out, int out_size) {
    const float* q  = (const float*)d_in[0];
    const float* k  = (const float*)d_in[1];
    const float* v  = (const float*)d_in[2];
    const float* rw = (const float*)d_in[3];
    float* out = (float*)d_out;

    float *za, *zb, *xx, *aa, *t1, *t2, *ql, *kl, *t3v, *yy, *a3, *a1;
    cudaGetSymbolAddress((void**)&za,  g_za);
    cudaGetSymbolAddress((void**)&zb,  g_zb);
    cudaGetSymbolAddress((void**)&xx,  g_x);
    cudaGetSymbolAddress((void**)&aa,  g_A);
    cudaGetSymbolAddress((void**)&t1,  g_T1);
    cudaGetSymbolAddress((void**)&t2,  g_T2);
    cudaGetSymbolAddress((void**)&ql,  g_ql);
    cudaGetSymbolAddress((void**)&kl,  g_kl);
    cudaGetSymbolAddress((void**)&t3v, g_t3v);
    cudaGetSymbolAddress((void**)&yy,  g_y);
    cudaGetSymbolAddress((void**)&a3,  g_attn3);
    cudaGetSymbolAddress((void**)&a1,  g_attn1);

    k_init<<<(Gb*Mm*Dd + 255)/256, 256>>>();
    k_landmark<<<(Gb*Mm*Dd + 255)/256, 256>>>(q, k);
    k_attn2<<<dim3(Mm, Gb), 256>>>();
    k_colmax<<<1, 256>>>();
    k_zinit<<<(Gb*Mm*Mm + 255)/256, 256>>>();

    // Moore-Penrose iterations (6x): A=X@Z; T1=A@A-7A+15I; T2=13I-A@T1; Z'=0.25*Z@T2
    float* zc = za; float* zn = zb;
    for (int it = 0; it < PITERS; it++) {
        dim3 gg(4, 4, Gb);
        k_gemm256<<<gg, 256>>>(xx, zc, aa, 1.f,  0.f,  0.f);
        k_gemm256<<<gg, 256>>>(aa, aa, t1, 1.f, -7.f, 15.f);
        k_gemm256<<<gg, 256>>>(aa, t1, t2, -1.f, 0.f, 13.f);
        k_gemm256<<<gg, 256>>>(zc, t2, zn, 0.25f, 0.f, 0.f);
        float* tmp = zc; zc = zn; zn = tmp;
    }
    // zc now holds attn2_inv

    // sim3 = ql @ k^T  -> softmax -> t3v = attn3 @ v  (split-K=8, atomic into zeroed t3v)
    k_gemm_nt<<<dim3(Nn/64, Mm/64, Gb), 256>>>(ql, (size_t)Mm*Dd, k, (size_t)Nn*Dd,
                                               a3, (size_t)Mm*Nn, Nn, 1.f);
    k_softmax<<<Gb*Mm, 256>>>(a3, Nn);
    k_av<<<dim3(8, Mm/64, Gb), 256>>>(a3, (size_t)Mm*Nn, Nn, v, (size_t)Nn*Dd,
                                      t3v, (size_t)Mm*Dd, Nn, 8, 1);
    // y = attn2_inv @ t3v
    k_av<<<dim3(1, Mm/64, Gb), 256>>>(zc, (size_t)Mm*Mm, Mm, t3v, (size_t)Mm*Dd,
                                      yy, (size_t)Mm*Dd, Mm, 1, 0);
    // sim1 = (q*scale) @ kl^T -> softmax -> out = attn1 @ y
    k_gemm_nt<<<dim3(Mm/64, Nn/64, Gb), 256>>>(q, (size_t)Nn*Dd, kl, (size_t)Mm*Dd,
                                               a1, (size_t)Nn*Mm, Mm, 0.125f);
    k_softmax<<<Gb*Nn, 256>>>(a1, Mm);
    k_av<<<dim3(1, Nn/64, Gb), 256>>>(a1, (size_t)Nn*Mm, Mm, yy, (size_t)Mm*Dd,
                                      out, (size_t)Nn*Dd, Mm, 1, 0);
    // residual depthwise conv
    k_conv<<<dim3(Nn/64, Gb), 256>>>(v, rw, out);
}

// round 3
// speedup vs baseline: 1.1239x; 1.1239x over previous
#include <cuda_runtime.h>
#include <cuda_bf16.h>
#include <cstdint>

#define Gb   32      // B*H
#define Hh   8
#define Nn   4096
#define Dd   64
#define Mm   256
#define Ll   16
#define PITERS 6
#define KC   33

// ---------------- scratch ----------------
__device__ float g_ql  [Gb*Mm*Dd];
__device__ float g_kl  [Gb*Mm*Dd];
__device__ float g_x   [Gb*Mm*Mm];
__device__ float g_za  [Gb*Mm*Mm];
__device__ float g_zb  [Gb*Mm*Mm];
__device__ float g_A   [Gb*Mm*Mm];
__device__ float g_T1  [Gb*Mm*Mm];
__device__ float g_T2  [Gb*Mm*Mm];
__device__ float g_t3v [Gb*Mm*Dd];
__device__ float g_y   [Gb*Mm*Dd];
__device__ float g_attn3[(size_t)Gb*Mm*Nn];
__device__ float g_attn1[(size_t)Gb*Nn*Mm];
__device__ float g_colsum[Gb*Mm];
__device__ unsigned int g_maxbits[2];

// ---------------- small helpers ----------------
__device__ __forceinline__ float blkmax(float v, float* sred) {
    int t = threadIdx.x; sred[t] = v; __syncthreads();
    for (int s = 128; s > 0; s >>= 1) { if (t < s) sred[t] = fmaxf(sred[t], sred[t+s]); __syncthreads(); }
    float r = sred[0]; __syncthreads(); return r;
}
__device__ __forceinline__ float blksum(float v, float* sred) {
    int t = threadIdx.x; sred[t] = v; __syncthreads();
    for (int s = 128; s > 0; s >>= 1) { if (t < s) sred[t] += sred[t+s]; __syncthreads(); }
    float r = sred[0]; __syncthreads(); return r;
}
__device__ __forceinline__ uint32_t smem_u32(const void* p) {
    uint32_t a;
    asm("{ .reg .u64 t; cvta.to.shared.u64 t, %1; cvt.u32.u64 %0, t; }" : "=r"(a) : "l"(p));
    return a;
}

// ---------------- mma.sync / ldmatrix (sm_80-era, valid on sm_100 base target) ----------------
__device__ __forceinline__ void mma_bf16(float* c, const uint32_t* a, const uint32_t* b) {
    asm volatile("mma.sync.aligned.m16n8k16.row.col.f32.bf16.bf16.f32 "
        "{%0,%1,%2,%3}, {%4,%5,%6,%7}, {%8,%9}, {%0,%1,%2,%3};"
        : "+f"(c[0]), "+f"(c[1]), "+f"(c[2]), "+f"(c[3])
        : "r"(a[0]), "r"(a[1]), "r"(a[2]), "r"(a[3]), "r"(b[0]), "r"(b[1]));
}
__device__ __forceinline__ void ldsm4(uint32_t* r, uint32_t addr) {
    asm volatile("ldmatrix.sync.aligned.m8n8.x4.shared.b16 {%0,%1,%2,%3}, [%4];"
        : "=r"(r[0]), "=r"(r[1]), "=r"(r[2]), "=r"(r[3]) : "r"(addr));
}

// ---------------- smem tile writers: fp32 -> (hi, lo) bf16 planes, xor-swizzled ----------------
// tile row = 64 bf16 = 128B = 8 chunks of 16B; swizzled chunk = chunk ^ (row & 7)
__device__ __forceinline__ void store_quad(char* hi, char* lo, int r, int c4, float4 v) {
    __nv_bfloat162 h01 = __floats2bfloat162_rn(v.x, v.y);
    __nv_bfloat162 h23 = __floats2bfloat162_rn(v.z, v.w);
    float rx = v.x - __bfloat162float(__low2bfloat16(h01));
    float ry = v.y - __bfloat162float(__high2bfloat16(h01));
    float rz = v.z - __bfloat162float(__low2bfloat16(h23));
    float rw = v.w - __bfloat162float(__high2bfloat16(h23));
    __nv_bfloat162 l01 = __floats2bfloat162_rn(rx, ry);
    __nv_bfloat162 l23 = __floats2bfloat162_rn(rz, rw);
    uint32_t chunk = (uint32_t)(c4 >> 3);
    uint32_t inner = (uint32_t)(c4 & 4) << 1;          // 0 or 8
    uint32_t addr = (uint32_t)r*128 + ((chunk ^ ((uint32_t)r & 7)) << 4) + inner;
    *(__nv_bfloat162*)(hi + addr)     = h01;
    *(__nv_bfloat162*)(hi + addr + 4) = h23;
    *(__nv_bfloat162*)(lo + addr)     = l01;
    *(__nv_bfloat162*)(lo + addr + 4) = l23;
}
__device__ __forceinline__ void store_one(char* hi, char* lo, int r, int col, float v) {
    __nv_bfloat16 h = __float2bfloat16(v);
    __nv_bfloat16 l = __float2bfloat16(v - __bfloat162float(h));
    uint32_t addr = (uint32_t)r*128 + ((((uint32_t)(col >> 3)) ^ ((uint32_t)r & 7)) << 4)
                  + ((uint32_t)(col & 7) << 1);
    *(__nv_bfloat16*)(hi + addr) = h;
    *(__nv_bfloat16*)(lo + addr) = l;
}

// ---------------- generic batched bf16x2 HMMA GEMM ----------------
// C[128, NT per CTA] = alpha*(A@B) + pc*A + qc*I
// A: [M,K] row-major fp32. B: TRANSB ? [K,N] row-major (A@B) : [N,K] row-major (A@B^T).
// grid = (ntiles | nsplit, mtiles, batch). nsplit>1 => split-K atomic accumulate, n0=0.
template<int NT, bool TRANSB>
__global__ void __launch_bounds__(256)
k_mma(const float* __restrict__ A, size_t sA, int lda,
      const float* __restrict__ B, size_t sB, int ldb,
      float* __restrict__ C, size_t sC, int ldc,
      int K, int nsplit, float alpha, float pc, float qc)
{
    constexpr int WARPS_N = NT / 32;          // 4 or 2
    constexpr int WM = 128 / (8 / WARPS_N);   // 64 or 32
    constexpr int MI = WM / 16;               // 4 or 2
    extern __shared__ char smraw[];
    char* sAh = smraw;
    char* sAl = smraw + 16384;
    char* sBh = smraw + 32768;
    char* sBl = sBh + NT*128;
    uint32_t sbase = smem_u32(smraw);
    const uint32_t offAh = 0, offAl = 16384, offBh = 32768, offBl = 32768u + NT*128;

    int tid = threadIdx.x, lane = tid & 31, wid = tid >> 5;
    int g = blockIdx.z;
    const float* Ag = A + (size_t)g*sA;
    const float* Bg = B + (size_t)g*sB;
    float*       Cg = C + (size_t)g*sC;
    int m0 = blockIdx.y * 128;
    int n0, kbeg, kend;
    if (nsplit > 1) { int ck = K / nsplit; n0 = 0; kbeg = blockIdx.x * ck; kend = kbeg + ck; }
    else            { n0 = blockIdx.x * NT; kbeg = 0; kend = K; }

    int wm = (wid / WARPS_N) * WM;
    int wn = (wid % WARPS_N) * 32;

    float acc[MI][4][4] = {};

    int nch = (kend - kbeg) >> 6;
    for (int ch = 0; ch < nch; ch++) {
        int k0 = kbeg + (ch << 6);
        // ---- A tile: 128 rows x 64 cols ----
        #pragma unroll
        for (int it = 0; it < 8; it++) {
            int i = it*256 + tid;                 // float4 index, 2048 total
            int r = i >> 4, c4 = (i & 15) << 2;
            float4 v = *(const float4*)(Ag + (size_t)(m0 + r)*lda + k0 + c4);
            store_quad(sAh, sAl, r, c4, v);
        }
        // ---- B tile: NT rows x 64 cols (smem layout [n][k]) ----
        if (TRANSB) {
            #pragma unroll
            for (int it = 0; it < NT/16; it++) {
                int e = (it*256 + tid) * 4;       // element index
                int n4 = e & (NT - 1), kk = e / NT;
                float4 v = *(const float4*)(Bg + (size_t)(k0 + kk)*ldb + n0 + n4);
                store_one(sBh, sBl, n4+0, kk, v.x);
                store_one(sBh, sBl, n4+1, kk, v.y);
                store_one(sBh, sBl, n4+2, kk, v.z);
                store_one(sBh, sBl, n4+3, kk, v.w);
            }
        } else {
            #pragma unroll
            for (int it = 0; it < NT/16; it++) {
                int i = it*256 + tid;
                int r = i >> 4, c4 = (i & 15) << 2;
                float4 v = *(const float4*)(Bg + (size_t)(n0 + r)*ldb + k0 + c4);
                store_quad(sBh, sBl, r, c4, v);
            }
        }
        __syncthreads();

        #pragma unroll
        for (int s = 0; s < 4; s++) {
            uint32_t ah[MI][4], al[MI][4], bh[2][4], bl[2][4];
            #pragma unroll
            for (int mi = 0; mi < MI; mi++) {
                int r = wm + mi*16 + (lane & 15);
                uint32_t c = 2*s + (lane >> 4);
                uint32_t off = (uint32_t)r*128 + ((c ^ ((uint32_t)r & 7)) << 4);
                ldsm4(ah[mi], sbase + offAh + off);
                ldsm4(al[mi], sbase + offAl + off);
            }
            #pragma unroll
            for (int ng = 0; ng < 2; ng++) {
                int r = wn + ng*16 + (lane & 15);
                uint32_t c = 2*s + (lane >> 4);
                uint32_t off = (uint32_t)r*128 + ((c ^ ((uint32_t)r & 7)) << 4);
                ldsm4(bh[ng], sbase + offBh + off);
                ldsm4(bl[ng], sbase + offBl + off);
            }
            #pragma unroll
            for (int mi = 0; mi < MI; mi++) {
                #pragma unroll
                for (int ni = 0; ni < 4; ni++) {
                    int ng = ni >> 1, h = ni & 1;
                    uint32_t bH[2] = { bh[ng][h], bh[ng][2+h] };
                    uint32_t bL[2] = { bl[ng][h], bl[ng][2+h] };
                    mma_bf16(acc[mi][ni], ah[mi], bH);   // Ah*Bh
                    mma_bf16(acc[mi][ni], ah[mi], bL);   // Ah*Bl
                    mma_bf16(acc[mi][ni], al[mi], bH);   // Al*Bh
                }
            }
        }
        __syncthreads();
    }

    // ---- epilogue from C fragments ----
    #pragma unroll
    for (int mi = 0; mi < MI; mi++) {
        #pragma unroll
        for (int ni = 0; ni < 4; ni++) {
            int gm = m0 + wm + mi*16 + (lane >> 2);
            int gn = n0 + wn + ni*8 + (lane & 3)*2;
            #pragma unroll
            for (int e = 0; e < 4; e++) {
                int rr = gm + (e >> 1)*8;
                int cc = gn + (e & 1);
                float vv = alpha * acc[mi][ni][e];
                if (pc != 0.f) vv += pc * Ag[(size_t)rr*lda + cc];
                if (qc != 0.f && rr == cc) vv += qc;
                if (nsplit > 1) atomicAdd(&Cg[(size_t)rr*ldc + cc], vv);
                else            Cg[(size_t)rr*ldc + cc] = vv;
            }
        }
    }
}

// ---------------- init / landmarks / attn2 / zinit ----------------
__global__ void k_init() {
    int idx = blockIdx.x*256 + threadIdx.x;
    if (idx < Gb*Mm*Dd) g_t3v[idx] = 0.f;
    if (idx < Gb*Mm)    g_colsum[idx] = 0.f;
    if (idx < 2)        g_maxbits[idx] = 0u;
}
__global__ void __launch_bounds__(256) k_landmark(const float* __restrict__ q,
                                                  const float* __restrict__ k) {
    int idx = blockIdx.x*256 + threadIdx.x;
    if (idx >= Gb*Mm*Dd) return;
    int d = idx & 63; int m = (idx >> 6) & 255; int g = idx >> 14;
    size_t base = ((size_t)g*Nn + (size_t)m*Ll)*Dd + d;
    float sq = 0.f, sk = 0.f;
    #pragma unroll
    for (int l = 0; l < Ll; l++) { sq += q[base + (size_t)l*Dd]; sk += k[base + (size_t)l*Dd]; }
    g_ql[idx] = sq * (0.125f / 16.f);
    g_kl[idx] = sk * (1.f / 16.f);
}
__global__ void __launch_bounds__(256) k_attn2() {
    __shared__ float qrow[Dd];
    __shared__ float sred[256];
    int i = blockIdx.x, g = blockIdx.y, j = threadIdx.x;
    if (threadIdx.x < Dd) qrow[threadIdx.x] = g_ql[((size_t)g*Mm + i)*Dd + threadIdx.x];
    __syncthreads();
    const float4* kr = (const float4*)(g_kl + ((size_t)g*Mm + j)*Dd);
    float s = 0.f;
    #pragma unroll
    for (int d4 = 0; d4 < 16; d4++) {
        float4 kv = kr[d4];
        s += qrow[d4*4+0]*kv.x + qrow[d4*4+1]*kv.y + qrow[d4*4+2]*kv.z + qrow[d4*4+3]*kv.w;
    }
    float mx = blkmax(s, sred);
    float e  = __expf(s - mx);
    float S  = blksum(e, sred);
    float val = e / S;
    g_x[((size_t)g*Mm + i)*Mm + j] = val;
    atomicAdd(&g_colsum[g*Mm + j], val);
    float rowsum = blksum(val, sred);
    if (threadIdx.x == 0) atomicMax(&g_maxbits[0], __float_as_uint(rowsum));
}
__global__ void k_colmax() {
    __shared__ float sred[256];
    float mx = 0.f;
    for (int i = threadIdx.x; i < Gb*Mm; i += 256) mx = fmaxf(mx, g_colsum[i]);
    mx = blkmax(mx, sred);
    if (threadIdx.x == 0) atomicMax(&g_maxbits[1], __float_as_uint(mx));
}
__global__ void __launch_bounds__(256) k_zinit() {
    int idx = blockIdx.x*256 + threadIdx.x;
    if (idx >= Gb*Mm*Mm) return;
    float denom = __uint_as_float(g_maxbits[0]) * __uint_as_float(g_maxbits[1]);
    int j = idx & 255; int i = (idx >> 8) & 255; int g = idx >> 16;
    g_za[idx] = g_x[((size_t)g*Mm + j)*Mm + i] / denom;
}

// ---------------- row softmax ----------------
__global__ void __launch_bounds__(256) k_softmax(float* __restrict__ mat, int cols) {
    __shared__ float buf[4096];
    __shared__ float sred[256];
    size_t r = blockIdx.x;
    float* p = mat + r * (size_t)cols;
    int t = threadIdx.x;
    float mx = -1e30f;
    for (int i = t; i < cols; i += 256) { float v = p[i]; buf[i] = v; mx = fmaxf(mx, v); }
    mx = blkmax(mx, sred);
    float s = 0.f;
    for (int i = t; i < cols; i += 256) { float e = __expf(buf[i] - mx); buf[i] = e; s += e; }
    s = blksum(s, sred);
    float inv = 1.f / s;
    for (int i = t; i < cols; i += 256) p[i] = buf[i] * inv;
}

// ---------------- depthwise residual conv ----------------
__global__ void __launch_bounds__(256) k_conv(const float* __restrict__ v,
                                              const float* __restrict__ w,
                                              float* __restrict__ out) {
    __shared__ float sv[96][64];
    __shared__ float sw[KC];
    int g = blockIdx.y, h = g & (Hh-1);
    int n0 = blockIdx.x * 64;
    const float* vb = v + (size_t)g*Nn*Dd;
    for (int idx = threadIdx.x; idx < 96*64; idx += 256) {
        int r = idx >> 6, d = idx & 63;
        int n = n0 - 16 + r;
        sv[r][d] = (n >= 0 && n < Nn) ? vb[(size_t)n*64 + d] : 0.f;
    }
    if (threadIdx.x < KC) sw[threadIdx.x] = w[h*KC + threadIdx.x];
    __syncthreads();
    for (int idx = threadIdx.x; idx < 64*64; idx += 256) {
        int r = idx >> 6, d = idx & 63;
        float acc = 0.f;
        #pragma unroll
        for (int t = 0; t < KC; t++) acc += sw[t] * sv[r+t][d];
        out[(size_t)g*Nn*Dd + (size_t)(n0+r)*64 + d] += acc;
    }
}

// ---------------- launch ----------------
#define DSM128 65536   // 16K*2 (A hi/lo) + 16K*2 (B hi/lo)
#define DSM64  49152   // 16K*2 + 8K*2

extern "C" void kernel_launch(void* const* d_in, const int* in_sizes, int n_in,
                              void* d_out, int out_size) {
    const float* q  = (const float*)d_in[0];
    const float* k  = (const float*)d_in[1];
    const float* v  = (const float*)d_in[2];
    const float* rw = (const float*)d_in[3];
    float* out = (float*)d_out;

    cudaFuncSetAttribute(k_mma<128,true>,  cudaFuncAttributeMaxDynamicSharedMemorySize, DSM128);
    cudaFuncSetAttribute(k_mma<128,false>, cudaFuncAttributeMaxDynamicSharedMemorySize, DSM128);
    cudaFuncSetAttribute(k_mma<64,true>,   cudaFuncAttributeMaxDynamicSharedMemorySize, DSM64);

    float *za, *zb, *xx, *aa, *t1, *t2, *ql, *kl, *t3v, *yy, *a3, *a1;
    cudaGetSymbolAddress((void**)&za,  g_za);
    cudaGetSymbolAddress((void**)&zb,  g_zb);
    cudaGetSymbolAddress((void**)&xx,  g_x);
    cudaGetSymbolAddress((void**)&aa,  g_A);
    cudaGetSymbolAddress((void**)&t1,  g_T1);
    cudaGetSymbolAddress((void**)&t2,  g_T2);
    cudaGetSymbolAddress((void**)&ql,  g_ql);
    cudaGetSymbolAddress((void**)&kl,  g_kl);
    cudaGetSymbolAddress((void**)&t3v, g_t3v);
    cudaGetSymbolAddress((void**)&yy,  g_y);
    cudaGetSymbolAddress((void**)&a3,  g_attn3);
    cudaGetSymbolAddress((void**)&a1,  g_attn1);

    k_init<<<(Gb*Mm*Dd + 255)/256, 256>>>();
    k_landmark<<<(Gb*Mm*Dd + 255)/256, 256>>>(q, k);
    k_attn2<<<dim3(Mm, Gb), 256>>>();
    k_colmax<<<1, 256>>>();
    k_zinit<<<(Gb*Mm*Mm + 255)/256, 256>>>();

    // Moore-Penrose: A=X@Z; T1=A@A-7A+15I; T2=13I-A@T1; Z'=0.25*Z@T2
    float* zc = za; float* zn = zb;
    const size_t sMM = (size_t)Mm*Mm;
    for (int it = 0; it < PITERS; it++) {
        dim3 gg(2, 2, Gb);
        k_mma<128,true><<<gg,256,DSM128>>>(xx, sMM, 256, zc, sMM, 256, aa, sMM, 256, 256, 1, 1.f,  0.f,  0.f);
        k_mma<128,true><<<gg,256,DSM128>>>(aa, sMM, 256, aa, sMM, 256, t1, sMM, 256, 256, 1, 1.f, -7.f, 15.f);
        k_mma<128,true><<<gg,256,DSM128>>>(aa, sMM, 256, t1, sMM, 256, t2, sMM, 256, 256, 1, -1.f, 0.f, 13.f);
        k_mma<128,true><<<gg,256,DSM128>>>(zc, sMM, 256, t2, sMM, 256, zn, sMM, 256, 256, 1, 0.25f, 0.f, 0.f);
        float* tmp = zc; zc = zn; zn = tmp;
    }

    // sim3 = ql @ k^T -> softmax -> t3v = attn3 @ v (split-K=8 atomic)
    k_mma<128,false><<<dim3(32,2,Gb),256,DSM128>>>(ql, (size_t)Mm*Dd, 64, k, (size_t)Nn*Dd, 64,
                                                   a3, (size_t)Mm*Nn, 4096, 64, 1, 1.f, 0.f, 0.f);
    k_softmax<<<Gb*Mm, 256>>>(a3, 4096);
    k_mma<64,true><<<dim3(8,2,Gb),256,DSM64>>>(a3, (size_t)Mm*Nn, 4096, v, (size_t)Nn*Dd, 64,
                                               t3v, (size_t)Mm*Dd, 64, 4096, 8, 1.f, 0.f, 0.f);
    // y = attn2_inv @ t3v
    k_mma<64,true><<<dim3(1,2,Gb),256,DSM64>>>(zc, sMM, 256, t3v, (size_t)Mm*Dd, 64,
                                               yy, (size_t)Mm*Dd, 64, 256, 1, 1.f, 0.f, 0.f);
    // sim1 = (q*scale) @ kl^T -> softmax -> out = attn1 @ y
    k_mma<128,false><<<dim3(2,32,Gb),256,DSM128>>>(q, (size_t)Nn*Dd, 64, kl, (size_t)Mm*Dd, 64,
                                                   a1, (size_t)Nn*Mm, 256, 64, 1, 0.125f, 0.f, 0.f);
    k_softmax<<<Gb*Nn, 256>>>(a1, 256);
    k_mma<64,true><<<dim3(1,32,Gb),256,DSM64>>>(a1, (size_t)Nn*Mm, 256, yy, (size_t)Mm*Dd, 64,
                                                out, (size_t)Nn*Dd, 64, 256, 1, 1.f, 0.f, 0.f);
    // residual depthwise conv
    k_conv<<<dim3(Nn/64, Gb), 256>>>(v, rw, out);
}

// round 4
// speedup vs baseline: 2.1366x; 1.9011x over previous
#include <cuda_runtime.h>
#include <cuda_bf16.h>
#include <cstdint>

#define Gb   32      // B*H
#define Hh   8
#define Nn   4096
#define Dd   64
#define Mm   256
#define Ll   16
#define PITERS 6
#define KC   33

// ---------------- scratch ----------------
__device__ float g_ql  [Gb*Mm*Dd];
__device__ float g_kl  [Gb*Mm*Dd];
__device__ float g_x   [Gb*Mm*Mm];
__device__ float g_za  [Gb*Mm*Mm];
__device__ float g_zb  [Gb*Mm*Mm];
__device__ float g_A   [Gb*Mm*Mm];
__device__ float g_T1  [Gb*Mm*Mm];
__device__ float g_T2  [Gb*Mm*Mm];
__device__ float g_t3v [Gb*Mm*Dd];
__device__ float g_y   [Gb*Mm*Dd];
__device__ float g_colsum[Gb*Mm];
__device__ unsigned int g_maxbits[2];

// ---------------- helpers ----------------
__device__ __forceinline__ float blkmax(float v, float* sred) {
    int t = threadIdx.x; sred[t] = v; __syncthreads();
    for (int s = 128; s > 0; s >>= 1) { if (t < s) sred[t] = fmaxf(sred[t], sred[t+s]); __syncthreads(); }
    float r = sred[0]; __syncthreads(); return r;
}
__device__ __forceinline__ float blksum(float v, float* sred) {
    int t = threadIdx.x; sred[t] = v; __syncthreads();
    for (int s = 128; s > 0; s >>= 1) { if (t < s) sred[t] += sred[t+s]; __syncthreads(); }
    float r = sred[0]; __syncthreads(); return r;
}
__device__ __forceinline__ uint32_t smem_u32(const void* p) {
    uint32_t a;
    asm("{ .reg .u64 t; cvta.to.shared.u64 t, %1; cvt.u32.u64 %0, t; }" : "=r"(a) : "l"(p));
    return a;
}
__device__ __forceinline__ void mma_bf16(float* c, const uint32_t* a, const uint32_t* b) {
    asm volatile("mma.sync.aligned.m16n8k16.row.col.f32.bf16.bf16.f32 "
        "{%0,%1,%2,%3}, {%4,%5,%6,%7}, {%8,%9}, {%0,%1,%2,%3};"
        : "+f"(c[0]), "+f"(c[1]), "+f"(c[2]), "+f"(c[3])
        : "r"(a[0]), "r"(a[1]), "r"(a[2]), "r"(a[3]), "r"(b[0]), "r"(b[1]));
}
__device__ __forceinline__ void ldsm4(uint32_t* r, uint32_t addr) {
    asm volatile("ldmatrix.sync.aligned.m8n8.x4.shared.b16 {%0,%1,%2,%3}, [%4];"
        : "=r"(r[0]), "=r"(r[1]), "=r"(r[2]), "=r"(r[3]) : "r"(addr));
}
__device__ __forceinline__ void ldsm4t(uint32_t* r, uint32_t addr) {
    asm volatile("ldmatrix.sync.aligned.m8n8.x4.trans.shared.b16 {%0,%1,%2,%3}, [%4];"
        : "=r"(r[0]), "=r"(r[1]), "=r"(r[2]), "=r"(r[3]) : "r"(addr));
}

// fp32 -> (hi,lo) bf16 planes; row=128B (64 bf16), chunk xor-swizzle
__device__ __forceinline__ void store_quad(char* hi, char* lo, int r, int c4, float4 v) {
    __nv_bfloat162 h01 = __floats2bfloat162_rn(v.x, v.y);
    __nv_bfloat162 h23 = __floats2bfloat162_rn(v.z, v.w);
    __nv_bfloat162 l01 = __floats2bfloat162_rn(v.x - __bfloat162float(__low2bfloat16(h01)),
                                               v.y - __bfloat162float(__high2bfloat16(h01)));
    __nv_bfloat162 l23 = __floats2bfloat162_rn(v.z - __bfloat162float(__low2bfloat16(h23)),
                                               v.w - __bfloat162float(__high2bfloat16(h23)));
    uint32_t chunk = (uint32_t)(c4 >> 3);
    uint32_t inner = (uint32_t)(c4 & 4) << 1;
    uint32_t addr = (uint32_t)r*128 + ((chunk ^ ((uint32_t)r & 7)) << 4) + inner;
    *(__nv_bfloat162*)(hi + addr)     = h01;
    *(__nv_bfloat162*)(hi + addr + 4) = h23;
    *(__nv_bfloat162*)(lo + addr)     = l01;
    *(__nv_bfloat162*)(lo + addr + 4) = l23;
}

// ---------------- batched bf16x2 HMMA GEMM (A@B, B global [K,N] row-major) ----------------
// C = alpha*(A@B) + pc*A + qc*I. tile 128 x NT. grid (N/NT, M/128, batch).
template<int NT>
__global__ void __launch_bounds__(256)
k_mma(const float* __restrict__ A, size_t sA, int lda,
      const float* __restrict__ B, size_t sB, int ldb,
      float* __restrict__ C, size_t sC, int ldc,
      int K, float alpha, float pc, float qc)
{
    constexpr int WARPS_N = NT / 32;          // 4 or 2
    constexpr int WM = 128 / (8 / WARPS_N);   // 64 or 32
    constexpr int MI = WM / 16;               // 4 or 2
    extern __shared__ char smraw[];
    char* sAh = smraw;
    char* sAl = smraw + 16384;
    char* sBh = smraw + 32768;
    char* sBl = sBh + NT*128;
    uint32_t sbase = smem_u32(smraw);
    const uint32_t offAh = 0, offAl = 16384, offBh = 32768, offBl = 32768u + NT*128;

    int tid = threadIdx.x, lane = tid & 31, wid = tid >> 5;
    int g = blockIdx.z;
    const float* Ag = A + (size_t)g*sA;
    const float* Bg = B + (size_t)g*sB;
    float*       Cg = C + (size_t)g*sC;
    int m0 = blockIdx.y * 128;
    int n0 = blockIdx.x * NT;
    int wm = (wid / WARPS_N) * WM;
    int wn = (wid % WARPS_N) * 32;

    float acc[MI][4][4] = {};

    int nch = K >> 6;
    for (int ch = 0; ch < nch; ch++) {
        int k0 = ch << 6;
        // A tile: 128 rows x 64 k
        #pragma unroll
        for (int it = 0; it < 8; it++) {
            int i = it*256 + tid;
            int r = i >> 4, c4 = (i & 15) << 2;
            float4 v = *(const float4*)(Ag + (size_t)(m0 + r)*lda + k0 + c4);
            store_quad(sAh, sAl, r, c4, v);
        }
        // B tile: [k=64 rows][NT n], subtiles of 64 n
        #pragma unroll
        for (int it = 0; it < NT/16; it++) {
            int i = it*256 + tid;
            int kk, n4;
            if (NT == 128) { kk = i >> 5; n4 = (i & 31) << 2; }
            else           { kk = i >> 4; n4 = (i & 15) << 2; }
            float4 bv = *(const float4*)(Bg + (size_t)(k0 + kk)*ldb + n0 + n4);
            int st = n4 >> 6;
            store_quad(sBh + st*8192, sBl + st*8192, kk, n4 & 63, bv);
        }
        __syncthreads();

        #pragma unroll
        for (int s = 0; s < 4; s++) {
            uint32_t ah[MI][4], al[MI][4], bh[2][4], bl[2][4];
            #pragma unroll
            for (int mi = 0; mi < MI; mi++) {
                int r = wm + mi*16 + (lane & 15);
                uint32_t c = 2*s + (lane >> 4);
                uint32_t off = (uint32_t)r*128 + ((c ^ ((uint32_t)r & 7)) << 4);
                ldsm4(ah[mi], sbase + offAh + off);
                ldsm4(al[mi], sbase + offAl + off);
            }
            #pragma unroll
            for (int ngl = 0; ngl < 2; ngl++) {
                uint32_t krow = (uint32_t)(s*16 + (lane & 15));
                uint32_t ci = (uint32_t)(wn >> 3) + 2*ngl + (lane >> 4);
                uint32_t off = (ci >> 3)*8192 + krow*128 + (((ci & 7) ^ (krow & 7)) << 4);
                ldsm4t(bh[ngl], sbase + offBh + off);
                ldsm4t(bl[ngl], sbase + offBl + off);
            }
            #pragma unroll
            for (int mi = 0; mi < MI; mi++) {
                #pragma unroll
                for (int ni = 0; ni < 4; ni++) {
                    int ngl = ni >> 1, h = ni & 1;
                    uint32_t bH[2] = { bh[ngl][2*h], bh[ngl][2*h+1] };
                    uint32_t bL[2] = { bl[ngl][2*h], bl[ngl][2*h+1] };
                    mma_bf16(acc[mi][ni], ah[mi], bH);
                    mma_bf16(acc[mi][ni], ah[mi], bL);
                    mma_bf16(acc[mi][ni], al[mi], bH);
                }
            }
        }
        __syncthreads();
    }

    #pragma unroll
    for (int mi = 0; mi < MI; mi++) {
        #pragma unroll
        for (int ni = 0; ni < 4; ni++) {
            int gm = m0 + wm + mi*16 + (lane >> 2);
            int gn = n0 + wn + ni*8 + (lane & 3)*2;
            #pragma unroll
            for (int e = 0; e < 4; e++) {
                int rr = gm + (e >> 1)*8;
                int cc = gn + (e & 1);
                float vv = alpha * acc[mi][ni][e];
                if (pc != 0.f) vv += pc * Ag[(size_t)rr*lda + cc];
                if (qc != 0.f && rr == cc) vv += qc;
                Cg[(size_t)rr*ldc + cc] = vv;
            }
        }
    }
}

// ---------------- fused flash attention: Out = softmax_row(A @ K^T) @ V (+conv) ----------------
// A: [rows][64] (64 rows per CTA), K/V chunks of 64 rows x 64 cols.
// smem: A hi/lo 16K | K hi/lo 16K | V hi/lo 16K | P hi/lo 16K | halo 96x68 f32 | w
#define OFF_AH 0
#define OFF_AL 8192
#define OFF_KH 16384
#define OFF_KL 24576
#define OFF_VH 32768
#define OFF_VL 40960
#define OFF_PH 49152
#define OFF_PL 57344
#define OFF_HALO 65536
#define OFF_W (65536 + 96*68*4)
#define DSM_FLASH_NC 65536
#define DSM_FLASH_CV (OFF_W + 160)

__global__ void __launch_bounds__(128)
k_flash(const float* __restrict__ A, size_t sAb,
        const float* __restrict__ Ksrc, const float* __restrict__ Vsrc, size_t sKb,
        float* __restrict__ Out, int nchunk, float ascale,
        const float* __restrict__ convV, const float* __restrict__ convW, int doconv)
{
    extern __shared__ char smraw[];
    uint32_t sbase = smem_u32(smraw);
    int tid = threadIdx.x, lane = tid & 31, w = tid >> 5;
    int rb = blockIdx.x, g = blockIdx.y;
    const float* Ag = A + (size_t)g*sAb + (size_t)rb*64*64;
    const float* Kg = Ksrc + (size_t)g*sKb;
    const float* Vg = Vsrc + (size_t)g*sKb;
    float*       Og = Out + (size_t)g*sAb + (size_t)rb*64*64;

    // A tile (scaled)
    #pragma unroll
    for (int it = 0; it < 8; it++) {
        int i = it*128 + tid;
        int r = i >> 4, c4 = (i & 15) << 2;
        float4 v = *(const float4*)(Ag + (size_t)r*64 + c4);
        v.x *= ascale; v.y *= ascale; v.z *= ascale; v.w *= ascale;
        store_quad(smraw + OFF_AH, smraw + OFF_AL, r, c4, v);
    }
    // conv halo (independent)
    if (doconv) {
        float* halo = (float*)(smraw + OFF_HALO);
        const float* vb = convV + (size_t)g*Nn*Dd;
        #pragma unroll
        for (int it = 0; it < 12; it++) {
            int i = it*128 + tid;
            int hr = i >> 4, c4 = (i & 15) << 2;
            int n = rb*64 - 16 + hr;
            float4 hv = (n >= 0 && n < Nn) ? *(const float4*)(vb + (size_t)n*64 + c4)
                                           : make_float4(0.f,0.f,0.f,0.f);
            *(float4*)&halo[hr*68 + c4] = hv;
        }
        if (tid < KC) ((float*)(smraw + OFF_W))[tid] = convW[(g & (Hh-1))*KC + tid];
    }

    float m0 = -1e30f, m1 = -1e30f, s0 = 0.f, s1 = 0.f;
    float O[8][4] = {};
    int rr0 = w*16 + (lane >> 2);
    int rr1 = rr0 + 8;
    uint32_t cbyte = (uint32_t)(lane & 3) << 2;

    for (int ch = 0; ch < nchunk; ch++) {
        __syncthreads();
        // K chunk [n][k], V chunk [k][n]
        #pragma unroll
        for (int it = 0; it < 8; it++) {
            int i = it*128 + tid;
            int r = i >> 4, c4 = (i & 15) << 2;
            float4 kv = *(const float4*)(Kg + (size_t)(ch*64 + r)*64 + c4);
            store_quad(smraw + OFF_KH, smraw + OFF_KL, r, c4, kv);
            float4 vv = *(const float4*)(Vg + (size_t)(ch*64 + r)*64 + c4);
            store_quad(smraw + OFF_VH, smraw + OFF_VL, r, c4, vv);
        }
        __syncthreads();

        // S = A @ K^T (64x64, warp = 16 rows)
        float S[8][4] = {};
        #pragma unroll
        for (int s = 0; s < 4; s++) {
            uint32_t ah[4], al_[4], kh[4][4], kl_[4][4];
            {
                int r = w*16 + (lane & 15);
                uint32_t c = 2*s + (lane >> 4);
                uint32_t off = (uint32_t)r*128 + ((c ^ ((uint32_t)r & 7)) << 4);
                ldsm4(ah, sbase + OFF_AH + off);
                ldsm4(al_, sbase + OFF_AL + off);
            }
            #pragma unroll
            for (int ng = 0; ng < 4; ng++) {
                int r = ng*16 + (lane & 15);
                uint32_t c = 2*s + (lane >> 4);
                uint32_t off = (uint32_t)r*128 + ((c ^ ((uint32_t)r & 7)) << 4);
                ldsm4(kh[ng], sbase + OFF_KH + off);
                ldsm4(kl_[ng], sbase + OFF_KL + off);
            }
            #pragma unroll
            for (int ng = 0; ng < 4; ng++) {
                #pragma unroll
                for (int h = 0; h < 2; h++) {
                    int ni = 2*ng + h;
                    uint32_t bH[2] = { kh[ng][h], kh[ng][2+h] };
                    uint32_t bL[2] = { kl_[ng][h], kl_[ng][2+h] };
                    mma_bf16(S[ni], ah, bH);
                    mma_bf16(S[ni], ah, bL);
                    mma_bf16(S[ni], al_, bH);
                }
            }
        }
        // online softmax
        float cm0 = -1e30f, cm1 = -1e30f;
        #pragma unroll
        for (int ni = 0; ni < 8; ni++) {
            cm0 = fmaxf(cm0, fmaxf(S[ni][0], S[ni][1]));
            cm1 = fmaxf(cm1, fmaxf(S[ni][2], S[ni][3]));
        }
        cm0 = fmaxf(cm0, __shfl_xor_sync(0xFFFFFFFFu, cm0, 1));
        cm0 = fmaxf(cm0, __shfl_xor_sync(0xFFFFFFFFu, cm0, 2));
        cm1 = fmaxf(cm1, __shfl_xor_sync(0xFFFFFFFFu, cm1, 1));
        cm1 = fmaxf(cm1, __shfl_xor_sync(0xFFFFFFFFu, cm1, 2));
        float nm0 = fmaxf(m0, cm0), nm1 = fmaxf(m1, cm1);
        float f0 = __expf(m0 - nm0), f1 = __expf(m1 - nm1);
        m0 = nm0; m1 = nm1;
        float rs0 = 0.f, rs1 = 0.f;
        #pragma unroll
        for (int ni = 0; ni < 8; ni++) {
            S[ni][0] = __expf(S[ni][0] - nm0); S[ni][1] = __expf(S[ni][1] - nm0);
            S[ni][2] = __expf(S[ni][2] - nm1); S[ni][3] = __expf(S[ni][3] - nm1);
            rs0 += S[ni][0] + S[ni][1];
            rs1 += S[ni][2] + S[ni][3];
        }
        rs0 += __shfl_xor_sync(0xFFFFFFFFu, rs0, 1); rs0 += __shfl_xor_sync(0xFFFFFFFFu, rs0, 2);
        rs1 += __shfl_xor_sync(0xFFFFFFFFu, rs1, 1); rs1 += __shfl_xor_sync(0xFFFFFFFFu, rs1, 2);
        s0 = s0*f0 + rs0; s1 = s1*f1 + rs1;
        #pragma unroll
        for (int ni = 0; ni < 8; ni++) {
            O[ni][0] *= f0; O[ni][1] *= f0; O[ni][2] *= f1; O[ni][3] *= f1;
        }
        // write P hi/lo (A-op layout [64 rows][64 k])
        #pragma unroll
        for (int ni = 0; ni < 8; ni++) {
            __nv_bfloat162 h0 = __floats2bfloat162_rn(S[ni][0], S[ni][1]);
            __nv_bfloat162 l0 = __floats2bfloat162_rn(S[ni][0] - __bfloat162float(__low2bfloat16(h0)),
                                                      S[ni][1] - __bfloat162float(__high2bfloat16(h0)));
            __nv_bfloat162 h1 = __floats2bfloat162_rn(S[ni][2], S[ni][3]);
            __nv_bfloat162 l1 = __floats2bfloat162_rn(S[ni][2] - __bfloat162float(__low2bfloat16(h1)),
                                                      S[ni][3] - __bfloat162float(__high2bfloat16(h1)));
            uint32_t a0 = OFF_PH + (uint32_t)rr0*128 + (((uint32_t)(ni ^ (rr0 & 7))) << 4) + cbyte;
            uint32_t a1 = OFF_PH + (uint32_t)rr1*128 + (((uint32_t)(ni ^ (rr1 & 7))) << 4) + cbyte;
            *(__nv_bfloat162*)(smraw + a0) = h0;
            *(__nv_bfloat162*)(smraw + a1) = h1;
            *(__nv_bfloat162*)(smraw + a0 + 8192) = l0;
            *(__nv_bfloat162*)(smraw + a1 + 8192) = l1;
        }
        __syncwarp();
        // O += P @ V  (V trans: [k][n])
        #pragma unroll
        for (int s = 0; s < 4; s++) {
            uint32_t ph[4], pl_[4], vh[4][4], vl_[4][4];
            {
                int r = w*16 + (lane & 15);
                uint32_t c = 2*s + (lane >> 4);
                uint32_t off = (uint32_t)r*128 + ((c ^ ((uint32_t)r & 7)) << 4);
                ldsm4(ph, sbase + OFF_PH + off);
                ldsm4(pl_, sbase + OFF_PL + off);
            }
            #pragma unroll
            for (int ng = 0; ng < 4; ng++) {
                uint32_t krow = (uint32_t)(s*16 + (lane & 15));
                uint32_t ci = (uint32_t)(2*ng) + (lane >> 4);
                uint32_t off = krow*128 + (((ci & 7) ^ (krow & 7)) << 4);
                ldsm4t(vh[ng], sbase + OFF_VH + off);
                ldsm4t(vl_[ng], sbase + OFF_VL + off);
            }
            #pragma unroll
            for (int ng = 0; ng < 4; ng++) {
                #pragma unroll
                for (int h = 0; h < 2; h++) {
                    int ni = 2*ng + h;
                    uint32_t bH[2] = { vh[ng][2*h], vh[ng][2*h+1] };
                    uint32_t bL[2] = { vl_[ng][2*h], vl_[ng][2*h+1] };
                    mma_bf16(O[ni], ph, bH);
                    mma_bf16(O[ni], ph, bL);
                    mma_bf16(O[ni], pl_, bH);
                }
            }
        }
    }

    // epilogue
    float inv0 = 1.f / s0, inv1 = 1.f / s1;
    float* halo = (float*)(smraw + OFF_HALO);
    float* swv  = (float*)(smraw + OFF_W);
    #pragma unroll
    for (int ni = 0; ni < 8; ni++) {
        int c0 = ni*8 + (lane & 3)*2;
        float v00 = O[ni][0]*inv0, v01 = O[ni][1]*inv0;
        float v10 = O[ni][2]*inv1, v11 = O[ni][3]*inv1;
        if (doconv) {
            float a00=0.f,a01=0.f,a10=0.f,a11=0.f;
            #pragma unroll
            for (int t = 0; t < KC; t++) {
                float wt = swv[t];
                a00 += wt * halo[(rr0 + t)*68 + c0];
                a01 += wt * halo[(rr0 + t)*68 + c0 + 1];
                a10 += wt * halo[(rr1 + t)*68 + c0];
                a11 += wt * halo[(rr1 + t)*68 + c0 + 1];
            }
            v00 += a00; v01 += a01; v10 += a10; v11 += a11;
        }
        float2 o0 = {v00, v01}, o1 = {v10, v11};
        *(float2*)(Og + (size_t)rr0*64 + c0) = o0;
        *(float2*)(Og + (size_t)rr1*64 + c0) = o1;
    }
}

// ---------------- preamble: init stats + landmarks ----------------
__global__ void __launch_bounds__(256) k_pre(const float* __restrict__ q,
                                             const float* __restrict__ k) {
    int idx = blockIdx.x*256 + threadIdx.x;
    if (idx < Gb*Mm) g_colsum[idx] = 0.f;
    if (idx < 2)     g_maxbits[idx] = 0u;
    if (idx >= Gb*Mm*Dd) return;
    int d = idx & 63; int m = (idx >> 6) & 255; int g = idx >> 14;
    size_t base = ((size_t)g*Nn + (size_t)m*Ll)*Dd + d;
    float sq = 0.f, sk = 0.f;
    #pragma unroll
    for (int l = 0; l < Ll; l++) { sq += q[base + (size_t)l*Dd]; sk += k[base + (size_t)l*Dd]; }
    g_ql[idx] = sq * (0.125f / 16.f);
    g_kl[idx] = sk * (1.f / 16.f);
}
__global__ void __launch_bounds__(256) k_attn2() {
    __shared__ float qrow[Dd];
    __shared__ float sred[256];
    int i = blockIdx.x, g = blockIdx.y, j = threadIdx.x;
    if (threadIdx.x < Dd) qrow[threadIdx.x] = g_ql[((size_t)g*Mm + i)*Dd + threadIdx.x];
    __syncthreads();
    const float4* kr = (const float4*)(g_kl + ((size_t)g*Mm + j)*Dd);
    float s = 0.f;
    #pragma unroll
    for (int d4 = 0; d4 < 16; d4++) {
        float4 kv = kr[d4];
        s += qrow[d4*4+0]*kv.x + qrow[d4*4+1]*kv.y + qrow[d4*4+2]*kv.z + qrow[d4*4+3]*kv.w;
    }
    float mx = blkmax(s, sred);
    float e  = __expf(s - mx);
    float S  = blksum(e, sred);
    float val = e / S;
    g_x[((size_t)g*Mm + i)*Mm + j] = val;
    atomicAdd(&g_colsum[g*Mm + j], val);
    float rowsum = blksum(val, sred);
    if (threadIdx.x == 0) atomicMax(&g_maxbits[0], __float_as_uint(rowsum));
}
__global__ void k_colmax() {
    __shared__ float sred[256];
    float mx = 0.f;
    for (int i = threadIdx.x; i < Gb*Mm; i += 256) mx = fmaxf(mx, g_colsum[i]);
    mx = blkmax(mx, sred);
    if (threadIdx.x == 0) atomicMax(&g_maxbits[1], __float_as_uint(mx));
}
__global__ void __launch_bounds__(256) k_zinit() {
    int idx = blockIdx.x*256 + threadIdx.x;
    if (idx >= Gb*Mm*Mm) return;
    float denom = __uint_as_float(g_maxbits[0]) * __uint_as_float(g_maxbits[1]);
    int j = idx & 255; int i = (idx >> 8) & 255; int g = idx >> 16;
    g_za[idx] = g_x[((size_t)g*Mm + j)*Mm + i] / denom;
}

// ---------------- launch ----------------
#define DSM128 65536
#define DSM64  49152

extern "C" void kernel_launch(void* const* d_in, const int* in_sizes, int n_in,
                              void* d_out, int out_size) {
    const float* q  = (const float*)d_in[0];
    const float* k  = (const float*)d_in[1];
    const float* v  = (const float*)d_in[2];
    const float* rw = (const float*)d_in[3];
    float* out = (float*)d_out;

    cudaFuncSetAttribute(k_mma<128>, cudaFuncAttributeMaxDynamicSharedMemorySize, DSM128);
    cudaFuncSetAttribute(k_mma<64>,  cudaFuncAttributeMaxDynamicSharedMemorySize, DSM64);
    cudaFuncSetAttribute(k_flash,    cudaFuncAttributeMaxDynamicSharedMemorySize, DSM_FLASH_CV);

    float *za, *zb, *xx, *aa, *t1, *t2, *ql, *kl, *t3v, *yy;
    cudaGetSymbolAddress((void**)&za,  g_za);
    cudaGetSymbolAddress((void**)&zb,  g_zb);
    cudaGetSymbolAddress((void**)&xx,  g_x);
    cudaGetSymbolAddress((void**)&aa,  g_A);
    cudaGetSymbolAddress((void**)&t1,  g_T1);
    cudaGetSymbolAddress((void**)&t2,  g_T2);
    cudaGetSymbolAddress((void**)&ql,  g_ql);
    cudaGetSymbolAddress((void**)&kl,  g_kl);
    cudaGetSymbolAddress((void**)&t3v, g_t3v);
    cudaGetSymbolAddress((void**)&yy,  g_y);

    k_pre<<<(Gb*Mm*Dd + 255)/256, 256>>>(q, k);          // launch 0
    k_attn2<<<dim3(Mm, Gb), 256>>>();                    // 1
    k_colmax<<<1, 256>>>();                              // 2
    k_zinit<<<(Gb*Mm*Mm + 255)/256, 256>>>();            // 3

    // Moore-Penrose: A=X@Z; T1=A@A-7A+15I; T2=13I-A@T1; Z'=0.25*Z@T2
    float* zc = za; float* zn = zb;
    const size_t sMM = (size_t)Mm*Mm;
    for (int it = 0; it < PITERS; it++) {
        dim3 gg(2, 2, Gb);
        k_mma<128><<<gg,256,DSM128>>>(xx, sMM, 256, zc, sMM, 256, aa, sMM, 256, 256, 1.f,  0.f,  0.f);
        k_mma<128><<<gg,256,DSM128>>>(aa, sMM, 256, aa, sMM, 256, t1, sMM, 256, 256, 1.f, -7.f, 15.f);
        k_mma<128><<<gg,256,DSM128>>>(aa, sMM, 256, t1, sMM, 256, t2, sMM, 256, 256, -1.f, 0.f, 13.f);
        k_mma<128><<<gg,256,DSM128>>>(zc, sMM, 256, t2, sMM, 256, zn, sMM, 256, 256, 0.25f, 0.f, 0.f);
        float* tmp = zc; zc = zn; zn = tmp;
    }

    // t3v = softmax(ql @ k^T) @ v  (flash, 64 chunks)
    k_flash<<<dim3(4, Gb), 128, DSM_FLASH_NC>>>(ql, (size_t)Mm*Dd, k, v, (size_t)Nn*Dd,
                                                t3v, Nn/64, 1.f, nullptr, nullptr, 0);
    // y = attn2_inv @ t3v
    k_mma<64><<<dim3(1, 2, Gb), 256, DSM64>>>(zc, sMM, 256, t3v, (size_t)Mm*Dd, 64,
                                              yy, (size_t)Mm*Dd, 64, 256, 1.f, 0.f, 0.f);
    // out = softmax(q*scale @ kl^T) @ y + conv(v)  (flash, 4 chunks, conv fused)
    k_flash<<<dim3(Nn/64, Gb), 128, DSM_FLASH_CV>>>(q, (size_t)Nn*Dd, kl, yy, (size_t)Mm*Dd,
                                                    out, Mm/64, 0.125f, v, rw, 1);
}

// round 5
// speedup vs baseline: 2.8408x; 1.3296x over previous
#include <cuda_runtime.h>
#include <cuda_bf16.h>
#include <cstdint>

#define Gb   32      // B*H
#define Hh   8
#define Nn   4096
#define Dd   64
#define Mm   256
#define Ll   16
#define PITERS 6
#define KC   33

// ---------------- scratch ----------------
__device__ float g_ql  [Gb*Mm*Dd];
__device__ float g_kl  [Gb*Mm*Dd];
__device__ float g_x   [Gb*Mm*Mm];
__device__ float g_za  [Gb*Mm*Mm];
__device__ float g_zb  [Gb*Mm*Mm];
__device__ float g_A   [Gb*Mm*Mm];
__device__ float g_T1  [Gb*Mm*Mm];
__device__ float g_T2  [Gb*Mm*Mm];
__device__ float g_t3v [Gb*Mm*Dd];
__device__ float g_y   [Gb*Mm*Dd];
__device__ float g_colsum[Gb*Mm];
__device__ unsigned int g_maxbits[2];

// ---------------- helpers ----------------
__device__ __forceinline__ float blkmax(float v, float* sred) {
    int t = threadIdx.x; sred[t] = v; __syncthreads();
    for (int s = 128; s > 0; s >>= 1) { if (t < s) sred[t] = fmaxf(sred[t], sred[t+s]); __syncthreads(); }
    float r = sred[0]; __syncthreads(); return r;
}
__device__ __forceinline__ float blksum(float v, float* sred) {
    int t = threadIdx.x; sred[t] = v; __syncthreads();
    for (int s = 128; s > 0; s >>= 1) { if (t < s) sred[t] += sred[t+s]; __syncthreads(); }
    float r = sred[0]; __syncthreads(); return r;
}
__device__ __forceinline__ uint32_t smem_u32(const void* p) {
    uint32_t a;
    asm("{ .reg .u64 t; cvta.to.shared.u64 t, %1; cvt.u32.u64 %0, t; }" : "=r"(a) : "l"(p));
    return a;
}
__device__ __forceinline__ void mma_bf16(float* c, const uint32_t* a, const uint32_t* b) {
    asm volatile("mma.sync.aligned.m16n8k16.row.col.f32.bf16.bf16.f32 "
        "{%0,%1,%2,%3}, {%4,%5,%6,%7}, {%8,%9}, {%0,%1,%2,%3};"
        : "+f"(c[0]), "+f"(c[1]), "+f"(c[2]), "+f"(c[3])
        : "r"(a[0]), "r"(a[1]), "r"(a[2]), "r"(a[3]), "r"(b[0]), "r"(b[1]));
}
__device__ __forceinline__ void ldsm4(uint32_t* r, uint32_t addr) {
    asm volatile("ldmatrix.sync.aligned.m8n8.x4.shared.b16 {%0,%1,%2,%3}, [%4];"
        : "=r"(r[0]), "=r"(r[1]), "=r"(r[2]), "=r"(r[3]) : "r"(addr));
}
__device__ __forceinline__ void ldsm4t(uint32_t* r, uint32_t addr) {
    asm volatile("ldmatrix.sync.aligned.m8n8.x4.trans.shared.b16 {%0,%1,%2,%3}, [%4];"
        : "=r"(r[0]), "=r"(r[1]), "=r"(r[2]), "=r"(r[3]) : "r"(addr));
}

// fp32 -> (hi,lo) bf16 planes; row=128B (64 bf16), chunk xor-swizzle
__device__ __forceinline__ void store_quad(char* hi, char* lo, int r, int c4, float4 v) {
    __nv_bfloat162 h01 = __floats2bfloat162_rn(v.x, v.y);
    __nv_bfloat162 h23 = __floats2bfloat162_rn(v.z, v.w);
    __nv_bfloat162 l01 = __floats2bfloat162_rn(v.x - __bfloat162float(__low2bfloat16(h01)),
                                               v.y - __bfloat162float(__high2bfloat16(h01)));
    __nv_bfloat162 l23 = __floats2bfloat162_rn(v.z - __bfloat162float(__low2bfloat16(h23)),
                                               v.w - __bfloat162float(__high2bfloat16(h23)));
    uint32_t chunk = (uint32_t)(c4 >> 3);
    uint32_t inner = (uint32_t)(c4 & 4) << 1;
    uint32_t addr = (uint32_t)r*128 + ((chunk ^ ((uint32_t)r & 7)) << 4) + inner;
    *(__nv_bfloat162*)(hi + addr)     = h01;
    *(__nv_bfloat162*)(hi + addr + 4) = h23;
    *(__nv_bfloat162*)(lo + addr)     = l01;
    *(__nv_bfloat162*)(lo + addr + 4) = l23;
}
// hi-plane-only variant (plain bf16)
__device__ __forceinline__ void store_quad_hi(char* hi, int r, int c4, float4 v) {
    __nv_bfloat162 h01 = __floats2bfloat162_rn(v.x, v.y);
    __nv_bfloat162 h23 = __floats2bfloat162_rn(v.z, v.w);
    uint32_t chunk = (uint32_t)(c4 >> 3);
    uint32_t inner = (uint32_t)(c4 & 4) << 1;
    uint32_t addr = (uint32_t)r*128 + ((chunk ^ ((uint32_t)r & 7)) << 4) + inner;
    *(__nv_bfloat162*)(hi + addr)     = h01;
    *(__nv_bfloat162*)(hi + addr + 4) = h23;
}

// ---------------- batched HMMA GEMM (A@B, B global [K,N] row-major) ----------------
// C = alpha*(A@B) + pc*A + qc*I. tile 128 x NT. grid (N/NT, M/128, batch).
// PREC==3: bf16x2 split (AhBh+AhBl+AlBh). PREC==1: plain bf16.
template<int NT, int PREC>
__global__ void __launch_bounds__(256)
k_mma(const float* __restrict__ A, size_t sA, int lda,
      const float* __restrict__ B, size_t sB, int ldb,
      float* __restrict__ C, size_t sC, int ldc,
      int K, float alpha, float pc, float qc)
{
    constexpr int WARPS_N = NT / 32;          // 4 or 2
    constexpr int WM = 128 / (8 / WARPS_N);   // 64 or 32
    constexpr int MI = WM / 16;               // 4 or 2
    constexpr int NB = NT / 16;               // B prefetch float4s per thread
    constexpr uint32_t offAh = 0;
    constexpr uint32_t offAl = 16384;                       // only PREC==3
    constexpr uint32_t offBh = (PREC == 3) ? 32768u : 16384u;
    constexpr uint32_t offBl = offBh + NT*128;              // only PREC==3
    extern __shared__ char smraw[];
    uint32_t sbase = smem_u32(smraw);

    int tid = threadIdx.x, lane = tid & 31, wid = tid >> 5;
    int g = blockIdx.z;
    const float* Ag = A + (size_t)g*sA;
    const float* Bg = B + (size_t)g*sB;
    float*       Cg = C + (size_t)g*sC;
    int m0 = blockIdx.y * 128;
    int n0 = blockIdx.x * NT;
    int wm = (wid / WARPS_N) * WM;
    int wn = (wid % WARPS_N) * 32;

    float acc[MI][4][4] = {};
    float4 pa[8], pb[NB];

    // prefetch chunk 0
    #pragma unroll
    for (int it = 0; it < 8; it++) {
        int i = it*256 + tid;
        int r = i >> 4, c4 = (i & 15) << 2;
        pa[it] = *(const float4*)(Ag + (size_t)(m0 + r)*lda + c4);
    }
    #pragma unroll
    for (int it = 0; it < NB; it++) {
        int i = it*256 + tid;
        int kk, n4;
        if (NT == 128) { kk = i >> 5; n4 = (i & 31) << 2; }
        else           { kk = i >> 4; n4 = (i & 15) << 2; }
        pb[it] = *(const float4*)(Bg + (size_t)kk*ldb + n0 + n4);
    }

    int nch = K >> 6;
    for (int ch = 0; ch < nch; ch++) {
        // store prefetched regs -> smem
        #pragma unroll
        for (int it = 0; it < 8; it++) {
            int i = it*256 + tid;
            int r = i >> 4, c4 = (i & 15) << 2;
            if (PREC == 3) store_quad(smraw + offAh, smraw + offAl, r, c4, pa[it]);
            else           store_quad_hi(smraw + offAh, r, c4, pa[it]);
        }
        #pragma unroll
        for (int it = 0; it < NB; it++) {
            int i = it*256 + tid;
            int kk, n4;
            if (NT == 128) { kk = i >> 5; n4 = (i & 31) << 2; }
            else           { kk = i >> 4; n4 = (i & 15) << 2; }
            int st = n4 >> 6;
            if (PREC == 3) store_quad(smraw + offBh + st*8192, smraw + offBl + st*8192, kk, n4 & 63, pb[it]);
            else           store_quad_hi(smraw + offBh + st*8192, kk, n4 & 63, pb[it]);
        }
        __syncthreads();

        // prefetch next chunk while MMAs run
        if (ch + 1 < nch) {
            int k0 = (ch + 1) << 6;
            #pragma unroll
            for (int it = 0; it < 8; it++) {
                int i = it*256 + tid;
                int r = i >> 4, c4 = (i & 15) << 2;
                pa[it] = *(const float4*)(Ag + (size_t)(m0 + r)*lda + k0 + c4);
            }
            #pragma unroll
            for (int it = 0; it < NB; it++) {
                int i = it*256 + tid;
                int kk, n4;
                if (NT == 128) { kk = i >> 5; n4 = (i & 31) << 2; }
                else           { kk = i >> 4; n4 = (i & 15) << 2; }
                pb[it] = *(const float4*)(Bg + (size_t)(k0 + kk)*ldb + n0 + n4);
            }
        }

        #pragma unroll
        for (int s = 0; s < 4; s++) {
            uint32_t ah[MI][4], al[MI][4], bh[2][4], bl[2][4];
            #pragma unroll
            for (int mi = 0; mi < MI; mi++) {
                int r = wm + mi*16 + (lane & 15);
                uint32_t c = 2*s + (lane >> 4);
                uint32_t off = (uint32_t)r*128 + ((c ^ ((uint32_t)r & 7)) << 4);
                ldsm4(ah[mi], sbase + offAh + off);
                if (PREC == 3) ldsm4(al[mi], sbase + offAl + off);
            }
            #pragma unroll
            for (int ngl = 0; ngl < 2; ngl++) {
                uint32_t krow = (uint32_t)(s*16 + (lane & 15));
                uint32_t ci = (uint32_t)(wn >> 3) + 2*ngl + (lane >> 4);
                uint32_t off = (ci >> 3)*8192 + krow*128 + (((ci & 7) ^ (krow & 7)) << 4);
                ldsm4t(bh[ngl], sbase + offBh + off);
                if (PREC == 3) ldsm4t(bl[ngl], sbase + offBl + off);
            }
            #pragma unroll
            for (int mi = 0; mi < MI; mi++) {
                #pragma unroll
                for (int ni = 0; ni < 4; ni++) {
                    int ngl = ni >> 1, h = ni & 1;
                    uint32_t bH[2] = { bh[ngl][2*h], bh[ngl][2*h+1] };
                    mma_bf16(acc[mi][ni], ah[mi], bH);
                    if (PREC == 3) {
                        uint32_t bL[2] = { bl[ngl][2*h], bl[ngl][2*h+1] };
                        mma_bf16(acc[mi][ni], ah[mi], bL);
                        mma_bf16(acc[mi][ni], al[mi], bH);
                    }
                }
            }
        }
        __syncthreads();
    }

    #pragma unroll
    for (int mi = 0; mi < MI; mi++) {
        #pragma unroll
        for (int ni = 0; ni < 4; ni++) {
            int gm = m0 + wm + mi*16 + (lane >> 2);
            int gn = n0 + wn + ni*8 + (lane & 3)*2;
            #pragma unroll
            for (int e = 0; e < 4; e++) {
                int rr = gm + (e >> 1)*8;
                int cc = gn + (e & 1);
                float vv = alpha * acc[mi][ni][e];
                if (pc != 0.f) vv += pc * Ag[(size_t)rr*lda + cc];
                if (qc != 0.f && rr == cc) vv += qc;
                Cg[(size_t)rr*ldc + cc] = vv;
            }
        }
    }
}

// ---------------- fused flash attention: Out = softmax_row(A @ K^T) @ V (+conv) ----------------
#define OFF_AH 0
#define OFF_AL 8192
#define OFF_KH 16384
#define OFF_KL 24576
#define OFF_VH 32768
#define OFF_VL 40960
#define OFF_PH 49152
#define OFF_PL 57344
#define OFF_HALO 65536
#define OFF_W (65536 + 96*68*4)
#define DSM_FLASH_NC 65536
#define DSM_FLASH_CV (OFF_W + 160)

__global__ void __launch_bounds__(128)
k_flash(const float* __restrict__ A, size_t sAb,
        const float* __restrict__ Ksrc, const float* __restrict__ Vsrc, size_t sKb,
        float* __restrict__ Out, int nchunk, float ascale,
        const float* __restrict__ convV, const float* __restrict__ convW, int doconv)
{
    extern __shared__ char smraw[];
    uint32_t sbase = smem_u32(smraw);
    int tid = threadIdx.x, lane = tid & 31, w = tid >> 5;
    int rb = blockIdx.x, g = blockIdx.y;
    const float* Ag = A + (size_t)g*sAb + (size_t)rb*64*64;
    const float* Kg = Ksrc + (size_t)g*sKb;
    const float* Vg = Vsrc + (size_t)g*sKb;
    float*       Og = Out + (size_t)g*sAb + (size_t)rb*64*64;

    // A tile (scaled)
    #pragma unroll
    for (int it = 0; it < 8; it++) {
        int i = it*128 + tid;
        int r = i >> 4, c4 = (i & 15) << 2;
        float4 v = *(const float4*)(Ag + (size_t)r*64 + c4);
        v.x *= ascale; v.y *= ascale; v.z *= ascale; v.w *= ascale;
        store_quad(smraw + OFF_AH, smraw + OFF_AL, r, c4, v);
    }
    // conv halo
    if (doconv) {
        float* halo = (float*)(smraw + OFF_HALO);
        const float* vb = convV + (size_t)g*Nn*Dd;
        #pragma unroll
        for (int it = 0; it < 12; it++) {
            int i = it*128 + tid;
            int hr = i >> 4, c4 = (i & 15) << 2;
            int n = rb*64 - 16 + hr;
            float4 hv = (n >= 0 && n < Nn) ? *(const float4*)(vb + (size_t)n*64 + c4)
                                           : make_float4(0.f,0.f,0.f,0.f);
            *(float4*)&halo[hr*68 + c4] = hv;
        }
        if (tid < KC) ((float*)(smraw + OFF_W))[tid] = convW[(g & (Hh-1))*KC + tid];
    }

    float m0 = -1e30f, m1 = -1e30f, s0 = 0.f, s1 = 0.f;
    float O[8][4] = {};
    int rr0 = w*16 + (lane >> 2);
    int rr1 = rr0 + 8;
    uint32_t cbyte = (uint32_t)(lane & 3) << 2;

    // prefetch chunk 0 K/V into regs
    float4 pk[8], pv[8];
    #pragma unroll
    for (int it = 0; it < 8; it++) {
        int i = it*128 + tid;
        int r = i >> 4, c4 = (i & 15) << 2;
        pk[it] = *(const float4*)(Kg + (size_t)r*64 + c4);
        pv[it] = *(const float4*)(Vg + (size_t)r*64 + c4);
    }

    for (int ch = 0; ch < nchunk; ch++) {
        __syncthreads();
        #pragma unroll
        for (int it = 0; it < 8; it++) {
            int i = it*128 + tid;
            int r = i >> 4, c4 = (i & 15) << 2;
            store_quad(smraw + OFF_KH, smraw + OFF_KL, r, c4, pk[it]);
            store_quad(smraw + OFF_VH, smraw + OFF_VL, r, c4, pv[it]);
        }
        __syncthreads();
        if (ch + 1 < nchunk) {
            #pragma unroll
            for (int it = 0; it < 8; it++) {
                int i = it*128 + tid;
                int r = i >> 4, c4 = (i & 15) << 2;
                pk[it] = *(const float4*)(Kg + (size_t)((ch+1)*64 + r)*64 + c4);
                pv[it] = *(const float4*)(Vg + (size_t)((ch+1)*64 + r)*64 + c4);
            }
        }

        // S = A @ K^T
        float S[8][4] = {};
        #pragma unroll
        for (int s = 0; s < 4; s++) {
            uint32_t ah[4], al_[4], kh[4][4], kl_[4][4];
            {
                int r = w*16 + (lane & 15);
                uint32_t c = 2*s + (lane >> 4);
                uint32_t off = (uint32_t)r*128 + ((c ^ ((uint32_t)r & 7)) << 4);
                ldsm4(ah, sbase + OFF_AH + off);
                ldsm4(al_, sbase + OFF_AL + off);
            }
            #pragma unroll
            for (int ng = 0; ng < 4; ng++) {
                int r = ng*16 + (lane & 15);
                uint32_t c = 2*s + (lane >> 4);
                uint32_t off = (uint32_t)r*128 + ((c ^ ((uint32_t)r & 7)) << 4);
                ldsm4(kh[ng], sbase + OFF_KH + off);
                ldsm4(kl_[ng], sbase + OFF_KL + off);
            }
            #pragma unroll
            for (int ng = 0; ng < 4; ng++) {
                #pragma unroll
                for (int h = 0; h < 2; h++) {
                    int ni = 2*ng + h;
                    uint32_t bH[2] = { kh[ng][h], kh[ng][2+h] };
                    uint32_t bL[2] = { kl_[ng][h], kl_[ng][2+h] };
                    mma_bf16(S[ni], ah, bH);
                    mma_bf16(S[ni], ah, bL);
                    mma_bf16(S[ni], al_, bH);
                }
            }
        }
        // online softmax
        float cm0 = -1e30f, cm1 = -1e30f;
        #pragma unroll
        for (int ni = 0; ni < 8; ni++) {
            cm0 = fmaxf(cm0, fmaxf(S[ni][0], S[ni][1]));
            cm1 = fmaxf(cm1, fmaxf(S[ni][2], S[ni][3]));
        }
        cm0 = fmaxf(cm0, __shfl_xor_sync(0xFFFFFFFFu, cm0, 1));
        cm0 = fmaxf(cm0, __shfl_xor_sync(0xFFFFFFFFu, cm0, 2));
        cm1 = fmaxf(cm1, __shfl_xor_sync(0xFFFFFFFFu, cm1, 1));
        cm1 = fmaxf(cm1, __shfl_xor_sync(0xFFFFFFFFu, cm1, 2));
        float nm0 = fmaxf(m0, cm0), nm1 = fmaxf(m1, cm1);
        float f0 = __expf(m0 - nm0), f1 = __expf(m1 - nm1);
        m0 = nm0; m1 = nm1;
        float rs0 = 0.f, rs1 = 0.f;
        #pragma unroll
        for (int ni = 0; ni < 8; ni++) {
            S[ni][0] = __expf(S[ni][0] - nm0); S[ni][1] = __expf(S[ni][1] - nm0);
            S[ni][2] = __expf(S[ni][2] - nm1); S[ni][3] = __expf(S[ni][3] - nm1);
            rs0 += S[ni][0] + S[ni][1];
            rs1 += S[ni][2] + S[ni][3];
        }
        rs0 += __shfl_xor_sync(0xFFFFFFFFu, rs0, 1); rs0 += __shfl_xor_sync(0xFFFFFFFFu, rs0, 2);
        rs1 += __shfl_xor_sync(0xFFFFFFFFu, rs1, 1); rs1 += __shfl_xor_sync(0xFFFFFFFFu, rs1, 2);
        s0 = s0*f0 + rs0; s1 = s1*f1 + rs1;
        #pragma unroll
        for (int ni = 0; ni < 8; ni++) {
            O[ni][0] *= f0; O[ni][1] *= f0; O[ni][2] *= f1; O[ni][3] *= f1;
        }
        // write P hi/lo
        #pragma unroll
        for (int ni = 0; ni < 8; ni++) {
            __nv_bfloat162 h0 = __floats2bfloat162_rn(S[ni][0], S[ni][1]);
            __nv_bfloat162 l0 = __floats2bfloat162_rn(S[ni][0] - __bfloat162float(__low2bfloat16(h0)),
                                                      S[ni][1] - __bfloat162float(__high2bfloat16(h0)));
            __nv_bfloat162 h1 = __floats2bfloat162_rn(S[ni][2], S[ni][3]);
            __nv_bfloat162 l1 = __floats2bfloat162_rn(S[ni][2] - __bfloat162float(__low2bfloat16(h1)),
                                                      S[ni][3] - __bfloat162float(__high2bfloat16(h1)));
            uint32_t a0 = OFF_PH + (uint32_t)rr0*128 + (((uint32_t)(ni ^ (rr0 & 7))) << 4) + cbyte;
            uint32_t a1 = OFF_PH + (uint32_t)rr1*128 + (((uint32_t)(ni ^ (rr1 & 7))) << 4) + cbyte;
            *(__nv_bfloat162*)(smraw + a0) = h0;
            *(__nv_bfloat162*)(smraw + a1) = h1;
            *(__nv_bfloat162*)(smraw + a0 + 8192) = l0;
            *(__nv_bfloat162*)(smraw + a1 + 8192) = l1;
        }
        __syncwarp();
        // O += P @ V
        #pragma unroll
        for (int s = 0; s < 4; s++) {
            uint32_t ph[4], pl_[4], vh[4][4], vl_[4][4];
            {
                int r = w*16 + (lane & 15);
                uint32_t c = 2*s + (lane >> 4);
                uint32_t off = (uint32_t)r*128 + ((c ^ ((uint32_t)r & 7)) << 4);
                ldsm4(ph, sbase + OFF_PH + off);
                ldsm4(pl_, sbase + OFF_PL + off);
            }
            #pragma unroll
            for (int ng = 0; ng < 4; ng++) {
                uint32_t krow = (uint32_t)(s*16 + (lane & 15));
                uint32_t ci = (uint32_t)(2*ng) + (lane >> 4);
                uint32_t off = krow*128 + (((ci & 7) ^ (krow & 7)) << 4);
                ldsm4t(vh[ng], sbase + OFF_VH + off);
                ldsm4t(vl_[ng], sbase + OFF_VL + off);
            }
            #pragma unroll
            for (int ng = 0; ng < 4; ng++) {
                #pragma unroll
                for (int h = 0; h < 2; h++) {
                    int ni = 2*ng + h;
                    uint32_t bH[2] = { vh[ng][2*h], vh[ng][2*h+1] };
                    uint32_t bL[2] = { vl_[ng][2*h], vl_[ng][2*h+1] };
                    mma_bf16(O[ni], ph, bH);
                    mma_bf16(O[ni], ph, bL);
                    mma_bf16(O[ni], pl_, bH);
                }
            }
        }
    }

    // epilogue
    float inv0 = 1.f / s0, inv1 = 1.f / s1;
    float* halo = (float*)(smraw + OFF_HALO);
    float* swv  = (float*)(smraw + OFF_W);
    #pragma unroll
    for (int ni = 0; ni < 8; ni++) {
        int c0 = ni*8 + (lane & 3)*2;
        float v00 = O[ni][0]*inv0, v01 = O[ni][1]*inv0;
        float v10 = O[ni][2]*inv1, v11 = O[ni][3]*inv1;
        if (doconv) {
            float a00=0.f,a01=0.f,a10=0.f,a11=0.f;
            #pragma unroll
            for (int t = 0; t < KC; t++) {
                float wt = swv[t];
                a00 += wt * halo[(rr0 + t)*68 + c0];
                a01 += wt * halo[(rr0 + t)*68 + c0 + 1];
                a10 += wt * halo[(rr1 + t)*68 + c0];
                a11 += wt * halo[(rr1 + t)*68 + c0 + 1];
            }
            v00 += a00; v01 += a01; v10 += a10; v11 += a11;
        }
        float2 o0 = {v00, v01}, o1 = {v10, v11};
        *(float2*)(Og + (size_t)rr0*64 + c0) = o0;
        *(float2*)(Og + (size_t)rr1*64 + c0) = o1;
    }
}

// ---------------- preamble ----------------
__global__ void __launch_bounds__(256) k_pre(const float* __restrict__ q,
                                             const float* __restrict__ k) {
    int idx = blockIdx.x*256 + threadIdx.x;
    if (idx < Gb*Mm) g_colsum[idx] = 0.f;
    if (idx < 2)     g_maxbits[idx] = 0u;
    if (idx >= Gb*Mm*Dd) return;
    int d = idx & 63; int m = (idx >> 6) & 255; int g = idx >> 14;
    size_t base = ((size_t)g*Nn + (size_t)m*Ll)*Dd + d;
    float sq = 0.f, sk = 0.f;
    #pragma unroll
    for (int l = 0; l < Ll; l++) { sq += q[base + (size_t)l*Dd]; sk += k[base + (size_t)l*Dd]; }
    g_ql[idx] = sq * (0.125f / 16.f);
    g_kl[idx] = sk * (1.f / 16.f);
}
__global__ void __launch_bounds__(256) k_attn2() {
    __shared__ float qrow[Dd];
    __shared__ float sred[256];
    int i = blockIdx.x, g = blockIdx.y, j = threadIdx.x;
    if (threadIdx.x < Dd) qrow[threadIdx.x] = g_ql[((size_t)g*Mm + i)*Dd + threadIdx.x];
    __syncthreads();
    const float4* kr = (const float4*)(g_kl + ((size_t)g*Mm + j)*Dd);
    float s = 0.f;
    #pragma unroll
    for (int d4 = 0; d4 < 16; d4++) {
        float4 kv = kr[d4];
        s += qrow[d4*4+0]*kv.x + qrow[d4*4+1]*kv.y + qrow[d4*4+2]*kv.z + qrow[d4*4+3]*kv.w;
    }
    float mx = blkmax(s, sred);
    float e  = __expf(s - mx);
    float S  = blksum(e, sred);
    float val = e / S;
    g_x[((size_t)g*Mm + i)*Mm + j] = val;
    atomicAdd(&g_colsum[g*Mm + j], val);
    float rowsum = blksum(val, sred);
    if (threadIdx.x == 0) atomicMax(&g_maxbits[0], __float_as_uint(rowsum));
}
__global__ void k_colmax() {
    __shared__ float sred[256];
    float mx = 0.f;
    for (int i = threadIdx.x; i < Gb*Mm; i += 256) mx = fmaxf(mx, g_colsum[i]);
    mx = blkmax(mx, sred);
    if (threadIdx.x == 0) atomicMax(&g_maxbits[1], __float_as_uint(mx));
}
// tiled transpose: za = x^T / denom
__global__ void __launch_bounds__(256) k_zinit() {
    __shared__ float t[32][33];
    int g = blockIdx.z;
    int i0 = blockIdx.y*32, j0 = blockIdx.x*32;
    int tx = threadIdx.x & 31, ty = threadIdx.x >> 5;
    const float* xp = g_x + (size_t)g*Mm*Mm;
    float* zp = g_za + (size_t)g*Mm*Mm;
    float denom = __uint_as_float(g_maxbits[0]) * __uint_as_float(g_maxbits[1]);
    float inv = 1.f / denom;
    #pragma unroll
    for (int r = 0; r < 32; r += 8)
        t[ty + r][tx] = xp[(size_t)(i0 + ty + r)*Mm + j0 + tx];
    __syncthreads();
    #pragma unroll
    for (int r = 0; r < 32; r += 8)
        zp[(size_t)(j0 + ty + r)*Mm + i0 + tx] = t[tx][ty + r] * inv;
}

// ---------------- launch ----------------
#define DSM128_3 65536
#define DSM128_1 32768
#define DSM64_3  49152

extern "C" void kernel_launch(void* const* d_in, const int* in_sizes, int n_in,
                              void* d_out, int out_size) {
    const float* q  = (const float*)d_in[0];
    const float* k  = (const float*)d_in[1];
    const float* v  = (const float*)d_in[2];
    const float* rw = (const float*)d_in[3];
    float* out = (float*)d_out;

    cudaFuncSetAttribute(k_mma<128,3>, cudaFuncAttributeMaxDynamicSharedMemorySize, DSM128_3);
    cudaFuncSetAttribute(k_mma<128,1>, cudaFuncAttributeMaxDynamicSharedMemorySize, DSM128_1);
    cudaFuncSetAttribute(k_mma<64,3>,  cudaFuncAttributeMaxDynamicSharedMemorySize, DSM64_3);
    cudaFuncSetAttribute(k_flash,      cudaFuncAttributeMaxDynamicSharedMemorySize, DSM_FLASH_CV);

    float *za, *zb, *xx, *aa, *t1, *t2, *ql, *kl, *t3v, *yy;
    cudaGetSymbolAddress((void**)&za,  g_za);
    cudaGetSymbolAddress((void**)&zb,  g_zb);
    cudaGetSymbolAddress((void**)&xx,  g_x);
    cudaGetSymbolAddress((void**)&aa,  g_A);
    cudaGetSymbolAddress((void**)&t1,  g_T1);
    cudaGetSymbolAddress((void**)&t2,  g_T2);
    cudaGetSymbolAddress((void**)&ql,  g_ql);
    cudaGetSymbolAddress((void**)&kl,  g_kl);
    cudaGetSymbolAddress((void**)&t3v, g_t3v);
    cudaGetSymbolAddress((void**)&yy,  g_y);

    k_pre<<<(Gb*Mm*Dd + 255)/256, 256>>>(q, k);
    k_attn2<<<dim3(Mm, Gb), 256>>>();
    k_colmax<<<1, 256>>>();
    k_zinit<<<dim3(8, 8, Gb), 256>>>();

    // Moore-Penrose: A=X@Z; T1=A@A-7A+15I; T2=13I-A@T1; Z'=0.25*Z@T2
    // iters 0..4 plain bf16 (self-correcting), iter 5 split precision.
    float* zc = za; float* zn = zb;
    const size_t sMM = (size_t)Mm*Mm;
    dim3 gg(2, 2, Gb);
    for (int it = 0; it < PITERS - 1; it++) {
        k_mma<128,1><<<gg,256,DSM128_1>>>(xx, sMM, 256, zc, sMM, 256, aa, sMM, 256, 256, 1.f,  0.f,  0.f);
        k_mma<128,1><<<gg,256,DSM128_1>>>(aa, sMM, 256, aa, sMM, 256, t1, sMM, 256, 256, 1.f, -7.f, 15.f);
        k_mma<128,1><<<gg,256,DSM128_1>>>(aa, sMM, 256, t1, sMM, 256, t2, sMM, 256, 256, -1.f, 0.f, 13.f);
        k_mma<128,1><<<gg,256,DSM128_1>>>(zc, sMM, 256, t2, sMM, 256, zn, sMM, 256, 256, 0.25f, 0.f, 0.f);
        float* tmp = zc; zc = zn; zn = tmp;
    }
    k_mma<128,3><<<gg,256,DSM128_3>>>(xx, sMM, 256, zc, sMM, 256, aa, sMM, 256, 256, 1.f,  0.f,  0.f);
    k_mma<128,3><<<gg,256,DSM128_3>>>(aa, sMM, 256, aa, sMM, 256, t1, sMM, 256, 256, 1.f, -7.f, 15.f);
    k_mma<128,3><<<gg,256,DSM128_3>>>(aa, sMM, 256, t1, sMM, 256, t2, sMM, 256, 256, -1.f, 0.f, 13.f);
    k_mma<128,3><<<gg,256,DSM128_3>>>(zc, sMM, 256, t2, sMM, 256, zn, sMM, 256, 256, 0.25f, 0.f, 0.f);
    { float* tmp = zc; zc = zn; zn = tmp; }

    // t3v = softmax(ql @ k^T) @ v
    k_flash<<<dim3(4, Gb), 128, DSM_FLASH_NC>>>(ql, (size_t)Mm*Dd, k, v, (size_t)Nn*Dd,
                                                t3v, Nn/64, 1.f, nullptr, nullptr, 0);
    // y = attn2_inv @ t3v
    k_mma<64,3><<<dim3(1, 2, Gb), 256, DSM64_3>>>(zc, sMM, 256, t3v, (size_t)Mm*Dd, 64,
                                                  yy, (size_t)Mm*Dd, 64, 256, 1.f, 0.f, 0.f);
    // out = softmax(q*scale @ kl^T) @ y + conv(v)
    k_flash<<<dim3(Nn/64, Gb), 128, DSM_FLASH_CV>>>(q, (size_t)Nn*Dd, kl, yy, (size_t)Mm*Dd,
                                                    out, Mm/64, 0.125f, v, rw, 1);
}